// round 1
// baseline (speedup 1.0000x reference)
#include <cuda_runtime.h>
#include <math.h>

// ---------------- problem constants ----------------
#define TOKENS   8192          // B*S = 4*2048
#define DMODEL   1024
#define NEXP     8
#define DFFN     2048
#define TOPK     2

// ---------------- GEMM tiling ----------------
#define BM 128
#define BN 128
#define BK 16
#define CAP (TOKENS*TOPK + NEXP*BM)    // 17408, tile-aligned worst case
#define ROW_TILES (CAP/BM)             // 136

// ---------------- device scratch (no cudaMalloc allowed) ----------------
__device__ float g_h[(size_t)CAP * DFFN];     // gelu(x@w1) scratch, ~142 MB
__device__ int   g_pair_tok[CAP];             // token id per sorted pair row (-1 = pad)
__device__ float g_pair_w[CAP];               // combine weight per pair row
__device__ int   g_cnt[NEXP];
__device__ int   g_cursor[NEXP];
__device__ int   g_off[NEXP + 1];             // BM-aligned expert segment offsets
__device__ float g_probs[TOKENS * NEXP];
__device__ float g_zsq[TOKENS];
__device__ int   g_sel[TOKENS * TOPK];
__device__ float g_selw[TOKENS * TOPK];

// ---------------- router: warp per token ----------------
__global__ __launch_bounds__(256) void router_kernel(const float* __restrict__ x,
                                                     const float* __restrict__ rw) {
    __shared__ float srw[NEXP * DMODEL];      // 32 KB
    int tid = threadIdx.x;
    for (int i = tid; i < NEXP * DMODEL; i += 256) srw[i] = rw[i];
    __syncthreads();

    int warp = tid >> 5, lane = tid & 31;
    int tok = blockIdx.x * 8 + warp;
    if (tok >= TOKENS) return;

    const float* xr = x + (size_t)tok * DMODEL;
    float acc[NEXP];
#pragma unroll
    for (int e = 0; e < NEXP; e++) acc[e] = 0.f;

    for (int i = lane; i < DMODEL; i += 32) {
        float xv = xr[i];
#pragma unroll
        for (int e = 0; e < NEXP; e++) acc[e] += xv * srw[e * DMODEL + i];
    }
#pragma unroll
    for (int off = 16; off; off >>= 1)
#pragma unroll
        for (int e = 0; e < NEXP; e++)
            acc[e] += __shfl_down_sync(0xffffffffu, acc[e], off);

    if (lane == 0) {
        float m = acc[0];
#pragma unroll
        for (int e = 1; e < NEXP; e++) m = fmaxf(m, acc[e]);
        float p[NEXP], s = 0.f;
#pragma unroll
        for (int e = 0; e < NEXP; e++) { p[e] = expf(acc[e] - m); s += p[e]; }
        float inv = 1.f / s;
#pragma unroll
        for (int e = 0; e < NEXP; e++) { p[e] *= inv; g_probs[tok * NEXP + e] = p[e]; }
        float lse = logf(s) + m;
        g_zsq[tok] = lse * lse;

        // top-2 (ties -> lowest index, matching lax.top_k)
        int e1 = 0;
#pragma unroll
        for (int e = 1; e < NEXP; e++) if (p[e] > p[e1]) e1 = e;
        int e2 = (e1 == 0) ? 1 : 0;
#pragma unroll
        for (int e = 0; e < NEXP; e++) if (e != e1 && p[e] > p[e2]) e2 = e;

        float wsum = p[e1] + p[e2];
        g_sel[tok * 2 + 0] = e1;  g_selw[tok * 2 + 0] = p[e1] / wsum;
        g_sel[tok * 2 + 1] = e2;  g_selw[tok * 2 + 1] = p[e2] / wsum;
        atomicAdd(&g_cnt[e1], 1);
        atomicAdd(&g_cnt[e2], 1);
    }
}

// ---------------- tile-aligned offsets ----------------
__global__ void offsets_kernel() {
    if (threadIdx.x == 0 && blockIdx.x == 0) {
        int o = 0;
#pragma unroll
        for (int e = 0; e < NEXP; e++) {
            g_off[e] = o;
            o += ((g_cnt[e] + BM - 1) / BM) * BM;
            g_cursor[e] = 0;
        }
        g_off[NEXP] = o;
    }
}

// ---------------- scatter pairs into expert segments ----------------
__global__ void scatter_kernel() {
    int t = blockIdx.x * blockDim.x + threadIdx.x;
    if (t >= TOKENS) return;
#pragma unroll
    for (int k = 0; k < TOPK; k++) {
        int e = g_sel[t * 2 + k];
        int pos = g_off[e] + atomicAdd(&g_cursor[e], 1);
        g_pair_tok[pos] = t;
        g_pair_w[pos]   = g_selw[t * 2 + k];
    }
}

// ---------------- fused expert GEMM (SIMT fp32, 128x128x16, 8x8/thread) ----------------
// FFN1: A = x gathered via pair tokens, W = w1, out = gelu -> g_h
// FFN2: A = g_h (direct rows),          W = w2, out = atomicAdd(w * acc) -> output
template <bool FFN1>
__global__ __launch_bounds__(256) void gemm_kernel(const float* __restrict__ Aglob,
                                                   const float* __restrict__ W,
                                                   float* __restrict__ out) {
    const int KDIM = FFN1 ? DMODEL : DFFN;
    const int LDB  = FFN1 ? (NEXP * DFFN) : DMODEL;

    __shared__ float As[BK][BM];
    __shared__ float Bs[BK][BN];
    __shared__ int   stok[BM];
    __shared__ float sw[BM];

    int row0 = blockIdx.x * BM;
    if (row0 >= g_off[NEXP]) return;

    int e = 0;
#pragma unroll
    for (int i = 0; i < NEXP; i++) if (row0 >= g_off[i + 1]) e = i + 1;

    int n0  = blockIdx.y * BN;
    int tid = threadIdx.x;
    if (tid < BM) {
        stok[tid] = g_pair_tok[row0 + tid];
        sw[tid]   = g_pair_w[row0 + tid];
    }
    __syncthreads();

    const float* Bbase = FFN1 ? (W + (size_t)e * DFFN + n0)
                              : (W + (size_t)e * DFFN * DMODEL + n0);

    float acc[8][8];
#pragma unroll
    for (int i = 0; i < 8; i++)
#pragma unroll
        for (int j = 0; j < 8; j++) acc[i][j] = 0.f;

    int tx  = tid & 15, ty = tid >> 4;
    int am  = tid & 127, akq = tid >> 7;        // A-load: m row, k-half
    int br  = tid >> 4,  bc  = (tid & 15) * 8;  // B-load: k row, n cols

    for (int k0 = 0; k0 < KDIM; k0 += BK) {
        float4 a0 = make_float4(0.f, 0.f, 0.f, 0.f), a1 = a0;
        if (FFN1) {
            int tok = stok[am];
            if (tok >= 0) {
                const float4* pa = (const float4*)(Aglob + (size_t)tok * DMODEL + k0 + akq * 8);
                a0 = pa[0]; a1 = pa[1];
            }
        } else {
            const float4* pa = (const float4*)(Aglob + (size_t)(row0 + am) * DFFN + k0 + akq * 8);
            a0 = pa[0]; a1 = pa[1];
        }
        As[akq * 8 + 0][am] = a0.x; As[akq * 8 + 1][am] = a0.y;
        As[akq * 8 + 2][am] = a0.z; As[akq * 8 + 3][am] = a0.w;
        As[akq * 8 + 4][am] = a1.x; As[akq * 8 + 5][am] = a1.y;
        As[akq * 8 + 6][am] = a1.z; As[akq * 8 + 7][am] = a1.w;

        const float4* pb = (const float4*)(Bbase + (size_t)(k0 + br) * LDB + bc);
        float4 b0 = pb[0], b1 = pb[1];
        *(float4*)&Bs[br][bc]     = b0;
        *(float4*)&Bs[br][bc + 4] = b1;

        __syncthreads();
#pragma unroll
        for (int kk = 0; kk < BK; kk++) {
            float a[8], b[8];
            *(float4*)&a[0] = *(const float4*)&As[kk][ty * 8];
            *(float4*)&a[4] = *(const float4*)&As[kk][ty * 8 + 4];
            *(float4*)&b[0] = *(const float4*)&Bs[kk][tx * 8];
            *(float4*)&b[4] = *(const float4*)&Bs[kk][tx * 8 + 4];
#pragma unroll
            for (int i = 0; i < 8; i++)
#pragma unroll
                for (int j = 0; j < 8; j++)
                    acc[i][j] = fmaf(a[i], b[j], acc[i][j]);
        }
        __syncthreads();
    }

    if (FFN1) {
#pragma unroll
        for (int i = 0; i < 8; i++) {
            int m = ty * 8 + i;
            float* dst = g_h + (size_t)(row0 + m) * DFFN + n0 + tx * 8;
            float v[8];
#pragma unroll
            for (int j = 0; j < 8; j++) {
                float u = acc[i][j];
                v[j] = 0.5f * u * (1.0f + erff(u * 0.70710678118654752440f));  // exact gelu
            }
            *(float4*)dst       = *(float4*)&v[0];
            *(float4*)(dst + 4) = *(float4*)&v[4];
        }
    } else {
#pragma unroll
        for (int i = 0; i < 8; i++) {
            int m = ty * 8 + i;
            int tok = stok[m];
            if (tok < 0) continue;
            float ws = sw[m];
            float* dst = out + (size_t)tok * DMODEL + n0 + tx * 8;
#pragma unroll
            for (int j = 0; j < 8; j++)
                atomicAdd(dst + j, ws * acc[i][j]);
        }
    }
}

// ---------------- deterministic aux-loss reduction ----------------
__global__ __launch_bounds__(256) void reduce_kernel(float* __restrict__ out, int out_size) {
    __shared__ float sbuf[256];
    int tid = threadIdx.x;

    // z loss
    float z = 0.f;
    for (int t = tid; t < TOKENS; t += 256) z += g_zsq[t];
    sbuf[tid] = z; __syncthreads();
    for (int s = 128; s; s >>= 1) { if (tid < s) sbuf[tid] += sbuf[tid + s]; __syncthreads(); }
    float zloss = sbuf[0] / (float)TOKENS;
    __syncthreads();

    // p_i
    float p[NEXP];
#pragma unroll
    for (int e = 0; e < NEXP; e++) p[e] = 0.f;
    for (int t = tid; t < TOKENS; t += 256) {
#pragma unroll
        for (int e = 0; e < NEXP; e++) p[e] += g_probs[t * NEXP + e];
    }
    float pi[NEXP];
#pragma unroll
    for (int e = 0; e < NEXP; e++) {
        sbuf[tid] = p[e]; __syncthreads();
        for (int s = 128; s; s >>= 1) { if (tid < s) sbuf[tid] += sbuf[tid + s]; __syncthreads(); }
        pi[e] = sbuf[0] / (float)TOKENS;
        __syncthreads();
    }

    if (tid == 0 && out_size >= TOKENS * DMODEL + 2 + NEXP) {
        float* tail = out + (size_t)TOKENS * DMODEL;
        tail[0] = zloss;
        float lb = 0.f;
#pragma unroll
        for (int e = 0; e < NEXP; e++) {
            float fi = (float)g_cnt[e] / (float)(TOKENS * TOPK);
            lb += fi * pi[e];
            tail[2 + e] = fi;
        }
        tail[1] = (float)NEXP * lb;
    }
}

// ---------------- launch ----------------
extern "C" void kernel_launch(void* const* d_in, const int* in_sizes, int n_in,
                              void* d_out, int out_size) {
    const float* x  = (const float*)d_in[0];
    const float* rw = (const float*)d_in[1];
    const float* w1 = (const float*)d_in[2];
    const float* w2 = (const float*)d_in[3];
    float* out = (float*)d_out;

    void *p_cnt, *p_ptok, *p_h;
    cudaGetSymbolAddress(&p_cnt, g_cnt);
    cudaGetSymbolAddress(&p_ptok, g_pair_tok);
    cudaGetSymbolAddress(&p_h, g_h);

    cudaMemsetAsync(out, 0, (size_t)TOKENS * DMODEL * sizeof(float));
    cudaMemsetAsync(p_cnt, 0, NEXP * sizeof(int));
    cudaMemsetAsync(p_ptok, 0xFF, CAP * sizeof(int));   // -1 pad tokens

    router_kernel<<<TOKENS / 8, 256>>>(x, rw);
    offsets_kernel<<<1, 32>>>();
    scatter_kernel<<<(TOKENS + 255) / 256, 256>>>();

    dim3 g1(ROW_TILES, DFFN / BN);   // 136 x 16
    gemm_kernel<true><<<g1, 256>>>(x, w1, out);

    dim3 g2(ROW_TILES, DMODEL / BN); // 136 x 8
    gemm_kernel<false><<<g2, 256>>>((const float*)p_h, w2, out);

    reduce_kernel<<<1, 256>>>(out, out_size);
}

// round 4
// speedup vs baseline: 1.5664x; 1.5664x over previous
#include <cuda_runtime.h>
#include <cuda.h>
#include <cuda_bf16.h>
#include <math.h>
#include <stdint.h>

// ---------------- problem constants ----------------
#define TOKENS   8192
#define DMODEL   1024
#define NEXP     8
#define DFFN     2048
#define TOPK     2

#define BM 128
#define BN 128
#define CAP (TOKENS*TOPK + NEXP*BM)    // 17408
#define ROW_TILES (CAP/BM)             // 136

#define BK 32
#define STAGES 4
#define LDA 36                          // padded words per 32-elem row
#define STG_WORDS (2 * BM * LDA)        // A + B per stage = 9216 words
#define SMEM_SZ (STAGES * STG_WORDS * 4 + 512)   // 147968 B

// ---------------- device scratch ----------------
__device__ __align__(1024) float g_xg[(size_t)CAP * DMODEL];
__device__ __align__(1024) float g_h[(size_t)CAP * DFFN];
__device__ __align__(1024) float g_y[(size_t)CAP * DMODEL];
__device__ __align__(1024) float g_w1t[(size_t)NEXP * DFFN * DMODEL];  // [(e,n)][k]
__device__ __align__(1024) float g_w2t[(size_t)NEXP * DMODEL * DFFN];  // [(e,n)][k]
__device__ int   g_pair_tok[CAP];
__device__ float g_pair_w[CAP];
__device__ int   g_tok2row[TOKENS * TOPK];
__device__ int   g_cnt[NEXP];
__device__ int   g_cursor[NEXP];
__device__ int   g_off[NEXP + 1];
__device__ float g_probs[TOKENS * NEXP];
__device__ float g_zsq[TOKENS];
__device__ int   g_sel[TOKENS * TOPK];
__device__ float g_selw[TOKENS * TOPK];

// ---------------- helpers ----------------
__device__ __forceinline__ uint32_t smem_u32(const void* p) {
    uint32_t a;
    asm("{ .reg .u64 t; cvta.to.shared.u64 t, %1; cvt.u32.u64 %0, t; }" : "=r"(a) : "l"(p));
    return a;
}

// split float2 -> bf16x2 hi + bf16x2 lo (error-compensated bf16x3 scheme)
__device__ __forceinline__ void split_bf16x2(float2 v, uint32_t& hi, uint32_t& lo) {
    __nv_bfloat162 h = __float22bfloat162_rn(v);
    float2 hf = __bfloat1622float2(h);
    float2 l = make_float2(v.x - hf.x, v.y - hf.y);
    __nv_bfloat162 lw = __float22bfloat162_rn(l);
    hi = *(uint32_t*)&h;
    lo = *(uint32_t*)&lw;
}

__device__ __forceinline__ void mma_bf16(float* c, const uint32_t* a, const uint32_t* b) {
    asm volatile(
        "mma.sync.aligned.m16n8k16.row.col.f32.bf16.bf16.f32 "
        "{%0,%1,%2,%3}, {%4,%5,%6,%7}, {%8,%9}, {%0,%1,%2,%3};"
        : "+f"(c[0]), "+f"(c[1]), "+f"(c[2]), "+f"(c[3])
        : "r"(a[0]), "r"(a[1]), "r"(a[2]), "r"(a[3]), "r"(b[0]), "r"(b[1]));
}

#define CP_ASYNC16(saddr, gaddr) \
    asm volatile("cp.async.cg.shared.global [%0], [%1], 16;" :: "r"(saddr), "l"(gaddr) : "memory")
#define CP_COMMIT() asm volatile("cp.async.commit_group;" ::: "memory")
#define CP_WAIT2()  asm volatile("cp.async.wait_group 2;" ::: "memory")

__device__ __forceinline__ float gelu_exact(float u) {
    return 0.5f * u * (1.0f + erff(u * 0.70710678118654752440f));
}

// ---------------- router: warp per token ----------------
__global__ __launch_bounds__(256) void router_kernel(const float* __restrict__ x,
                                                     const float* __restrict__ rw) {
    __shared__ float srw[NEXP * DMODEL];
    int tid = threadIdx.x;
    for (int i = tid; i < NEXP * DMODEL; i += 256) srw[i] = rw[i];
    __syncthreads();

    int warp = tid >> 5, lane = tid & 31;
    int tok = blockIdx.x * 8 + warp;
    if (tok >= TOKENS) return;

    const float* xr = x + (size_t)tok * DMODEL;
    float acc[NEXP];
#pragma unroll
    for (int e = 0; e < NEXP; e++) acc[e] = 0.f;
    for (int i = lane; i < DMODEL; i += 32) {
        float xv = xr[i];
#pragma unroll
        for (int e = 0; e < NEXP; e++) acc[e] += xv * srw[e * DMODEL + i];
    }
#pragma unroll
    for (int off = 16; off; off >>= 1)
#pragma unroll
        for (int e = 0; e < NEXP; e++)
            acc[e] += __shfl_down_sync(0xffffffffu, acc[e], off);

    if (lane == 0) {
        float m = acc[0];
#pragma unroll
        for (int e = 1; e < NEXP; e++) m = fmaxf(m, acc[e]);
        float p[NEXP], s = 0.f;
#pragma unroll
        for (int e = 0; e < NEXP; e++) { p[e] = expf(acc[e] - m); s += p[e]; }
        float inv = 1.f / s;
#pragma unroll
        for (int e = 0; e < NEXP; e++) { p[e] *= inv; g_probs[tok * NEXP + e] = p[e]; }
        float lse = logf(s) + m;
        g_zsq[tok] = lse * lse;

        int e1 = 0;
#pragma unroll
        for (int e = 1; e < NEXP; e++) if (p[e] > p[e1]) e1 = e;
        int e2 = (e1 == 0) ? 1 : 0;
#pragma unroll
        for (int e = 0; e < NEXP; e++) if (e != e1 && p[e] > p[e2]) e2 = e;

        float wsum = p[e1] + p[e2];
        g_sel[tok * 2 + 0] = e1;  g_selw[tok * 2 + 0] = p[e1] / wsum;
        g_sel[tok * 2 + 1] = e2;  g_selw[tok * 2 + 1] = p[e2] / wsum;
        atomicAdd(&g_cnt[e1], 1);
        atomicAdd(&g_cnt[e2], 1);
    }
}

__global__ void offsets_kernel() {
    if (threadIdx.x == 0 && blockIdx.x == 0) {
        int o = 0;
#pragma unroll
        for (int e = 0; e < NEXP; e++) {
            g_off[e] = o;
            o += ((g_cnt[e] + BM - 1) / BM) * BM;
            g_cursor[e] = 0;
        }
        g_off[NEXP] = o;
    }
}

__global__ void scatter_kernel() {
    int t = blockIdx.x * blockDim.x + threadIdx.x;
    if (t >= TOKENS) return;
#pragma unroll
    for (int k = 0; k < TOPK; k++) {
        int e = g_sel[t * 2 + k];
        int pos = g_off[e] + atomicAdd(&g_cursor[e], 1);
        g_pair_tok[pos] = t;
        g_pair_w[pos]   = g_selw[t * 2 + k];
        g_tok2row[t * 2 + k] = pos;
    }
}

__global__ __launch_bounds__(128) void gather_kernel(const float* __restrict__ x) {
    int r = blockIdx.x;
    int tok = g_pair_tok[r];
    float4* dst = (float4*)(g_xg + (size_t)r * DMODEL);
    if (tok >= 0) {
        const float4* src = (const float4*)(x + (size_t)tok * DMODEL);
        for (int i = threadIdx.x; i < DMODEL / 4; i += 128) dst[i] = src[i];
    } else {
        float4 z = make_float4(0.f, 0.f, 0.f, 0.f);
        for (int i = threadIdx.x; i < DMODEL / 4; i += 128) dst[i] = z;
    }
}

// w1 [1024][16384] -> g_w1t [16384][1024]
__global__ __launch_bounds__(256) void transpose_w1(const float* __restrict__ in) {
    __shared__ float t[32][33];
    int c0 = blockIdx.x * 32, r0 = blockIdx.y * 32;
    int x = threadIdx.x, y = threadIdx.y;
#pragma unroll
    for (int i = 0; i < 32; i += 8) t[y + i][x] = in[(size_t)(r0 + y + i) * 16384 + c0 + x];
    __syncthreads();
#pragma unroll
    for (int i = 0; i < 32; i += 8) g_w1t[(size_t)(c0 + y + i) * 1024 + r0 + x] = t[x][y + i];
}

// w2 [e][2048][1024] -> g_w2t [e][1024][2048]
__global__ __launch_bounds__(256) void transpose_w2(const float* __restrict__ in) {
    __shared__ float t[32][33];
    int e = blockIdx.z;
    int n0 = blockIdx.x * 32, k0 = blockIdx.y * 32;
    int x = threadIdx.x, y = threadIdx.y;
#pragma unroll
    for (int i = 0; i < 32; i += 8)
        t[y + i][x] = in[((size_t)e * 2048 + k0 + y + i) * 1024 + n0 + x];
    __syncthreads();
#pragma unroll
    for (int i = 0; i < 32; i += 8)
        g_w2t[((size_t)e * 1024 + n0 + y + i) * 2048 + k0 + x] = t[x][y + i];
}

// ================= GEMM: 128x128 tile, bf16x3 mma.sync =================
// A[row][k] row-major stride KDIM; B[n][k] row-major stride KDIM. D = A @ B^T.
template <bool FFN1>
__global__ __launch_bounds__(128, 1) void gemm_tc(const float* __restrict__ Ag,
                                                  const float* __restrict__ Bg) {
    const int KDIM = FFN1 ? DMODEL : DFFN;
    int row0 = blockIdx.x * BM;
    if (row0 >= g_off[NEXP]) return;
    int e = 0;
#pragma unroll
    for (int i = 0; i < NEXP; i++) if (row0 >= g_off[i + 1]) e = i + 1;

    const int n0 = blockIdx.y * BN;
    const int ybase = (FFN1 ? e * DFFN : e * DMODEL) + n0;
    int tid = threadIdx.x, wid = tid >> 5, lane = tid & 31;

    extern __shared__ float smf[];
    float* swt = smf + STAGES * STG_WORDS;
    if (!FFN1) swt[tid] = g_pair_w[row0 + tid];
    __syncthreads();

    const float* Abase = Ag + (size_t)row0 * KDIM;
    const float* Bbase = Bg + (size_t)ybase * KDIM;

    int wr = wid >> 1, wc = wid & 1;          // 2x2 warp grid, 64x64 warp tiles
    int gid = lane >> 2, tig = lane & 3;

    float c[4][8][4];
#pragma unroll
    for (int i = 0; i < 4; i++)
#pragma unroll
        for (int j = 0; j < 8; j++)
#pragma unroll
            for (int q = 0; q < 4; q++) c[i][j][q] = 0.f;

    const int NCH = KDIM / BK;
    uint32_t smf_base = smem_u32(smf);

    auto fill = [&](int st, int kc) {
        uint32_t sA = smf_base + st * STG_WORDS * 4;
        uint32_t sB = sA + BM * LDA * 4;
        int kofs = kc * BK;
#pragma unroll
        for (int i = 0; i < 8; i++) {
            int q = tid * 8 + i;
            int row = q >> 3, kq = (q & 7) * 4;
            CP_ASYNC16(sA + (row * LDA + kq) * 4, Abase + (size_t)row * KDIM + kofs + kq);
        }
#pragma unroll
        for (int i = 0; i < 8; i++) {
            int q = tid * 8 + i;
            int row = q >> 3, kq = (q & 7) * 4;
            CP_ASYNC16(sB + (row * LDA + kq) * 4, Bbase + (size_t)row * KDIM + kofs + kq);
        }
    };

#pragma unroll
    for (int s = 0; s < STAGES - 1; s++) { fill(s, s); CP_COMMIT(); }

    for (int kc = 0; kc < NCH; kc++) {
        CP_WAIT2();
        __syncthreads();
        if (kc + STAGES - 1 < NCH) fill((kc + STAGES - 1) % STAGES, kc + STAGES - 1);
        CP_COMMIT();

        const float* As = smf + (kc % STAGES) * STG_WORDS;
        const float* Bs = As + BM * LDA;
#pragma unroll
        for (int kk = 0; kk < 2; kk++) {
            int k0 = kk * 16;
            uint32_t ah[4][4], al[4][4], bh[8][2], bl[8][2];
#pragma unroll
            for (int i = 0; i < 4; i++) {
                int mb = wr * 64 + i * 16;
                float2 v0 = *(const float2*)&As[(mb + gid)     * LDA + k0 + 2 * tig];
                float2 v1 = *(const float2*)&As[(mb + gid + 8) * LDA + k0 + 2 * tig];
                float2 v2 = *(const float2*)&As[(mb + gid)     * LDA + k0 + 2 * tig + 8];
                float2 v3 = *(const float2*)&As[(mb + gid + 8) * LDA + k0 + 2 * tig + 8];
                split_bf16x2(v0, ah[i][0], al[i][0]);
                split_bf16x2(v1, ah[i][1], al[i][1]);
                split_bf16x2(v2, ah[i][2], al[i][2]);
                split_bf16x2(v3, ah[i][3], al[i][3]);
            }
#pragma unroll
            for (int j = 0; j < 8; j++) {
                int nb = wc * 64 + j * 8;
                float2 w0 = *(const float2*)&Bs[(nb + gid) * LDA + k0 + 2 * tig];
                float2 w1 = *(const float2*)&Bs[(nb + gid) * LDA + k0 + 2 * tig + 8];
                split_bf16x2(w0, bh[j][0], bl[j][0]);
                split_bf16x2(w1, bh[j][1], bl[j][1]);
            }
#pragma unroll
            for (int i = 0; i < 4; i++)
#pragma unroll
                for (int j = 0; j < 8; j++) {
                    mma_bf16(c[i][j], ah[i], bh[j]);   // hi*hi
                    mma_bf16(c[i][j], ah[i], bl[j]);   // hi*lo
                    mma_bf16(c[i][j], al[i], bh[j]);   // lo*hi
                }
        }
        __syncthreads();
    }

    // epilogue (m16n8 c-fragment: c0,c1 at row g cols 2tig,2tig+1; c2,c3 at row g+8)
#pragma unroll
    for (int i = 0; i < 4; i++) {
        int mr0 = wr * 64 + i * 16 + gid;
        int mr1 = mr0 + 8;
        if (FFN1) {
            float* h0 = g_h + (size_t)(row0 + mr0) * DFFN + n0;
            float* h1 = g_h + (size_t)(row0 + mr1) * DFFN + n0;
#pragma unroll
            for (int j = 0; j < 8; j++) {
                int col = wc * 64 + j * 8 + tig * 2;
                *(float2*)(h0 + col) = make_float2(gelu_exact(c[i][j][0]), gelu_exact(c[i][j][1]));
                *(float2*)(h1 + col) = make_float2(gelu_exact(c[i][j][2]), gelu_exact(c[i][j][3]));
            }
        } else {
            float ws0 = swt[mr0], ws1 = swt[mr1];
            float* y0 = g_y + (size_t)(row0 + mr0) * DMODEL + n0;
            float* y1 = g_y + (size_t)(row0 + mr1) * DMODEL + n0;
#pragma unroll
            for (int j = 0; j < 8; j++) {
                int col = wc * 64 + j * 8 + tig * 2;
                *(float2*)(y0 + col) = make_float2(ws0 * c[i][j][0], ws0 * c[i][j][1]);
                *(float2*)(y1 + col) = make_float2(ws1 * c[i][j][2], ws1 * c[i][j][3]);
            }
        }
    }
}

// ---------------- combine ----------------
__global__ __launch_bounds__(128) void combine_kernel(float* __restrict__ out) {
    int t = blockIdx.x;
    int ra = g_tok2row[t * 2 + 0];
    int rb = g_tok2row[t * 2 + 1];
    const float4* ya = (const float4*)(g_y + (size_t)ra * DMODEL);
    const float4* yb = (const float4*)(g_y + (size_t)rb * DMODEL);
    float4* o = (float4*)(out + (size_t)t * DMODEL);
    for (int i = threadIdx.x; i < DMODEL / 4; i += 128) {
        float4 a = ya[i], b = yb[i];
        o[i] = make_float4(a.x + b.x, a.y + b.y, a.z + b.z, a.w + b.w);
    }
}

// ---------------- aux losses ----------------
__global__ __launch_bounds__(256) void reduce_kernel(float* __restrict__ out, int out_size) {
    __shared__ float sbuf[256];
    int tid = threadIdx.x;

    float z = 0.f;
    for (int t = tid; t < TOKENS; t += 256) z += g_zsq[t];
    sbuf[tid] = z; __syncthreads();
    for (int s = 128; s; s >>= 1) { if (tid < s) sbuf[tid] += sbuf[tid + s]; __syncthreads(); }
    float zloss = sbuf[0] / (float)TOKENS;
    __syncthreads();

    float p[NEXP];
#pragma unroll
    for (int e = 0; e < NEXP; e++) p[e] = 0.f;
    for (int t = tid; t < TOKENS; t += 256) {
#pragma unroll
        for (int e = 0; e < NEXP; e++) p[e] += g_probs[t * NEXP + e];
    }
    float pi[NEXP];
#pragma unroll
    for (int e = 0; e < NEXP; e++) {
        sbuf[tid] = p[e]; __syncthreads();
        for (int s = 128; s; s >>= 1) { if (tid < s) sbuf[tid] += sbuf[tid + s]; __syncthreads(); }
        pi[e] = sbuf[0] / (float)TOKENS;
        __syncthreads();
    }

    if (tid == 0 && out_size >= TOKENS * DMODEL + 2 + NEXP) {
        float* tail = out + (size_t)TOKENS * DMODEL;
        tail[0] = zloss;
        float lb = 0.f;
#pragma unroll
        for (int e = 0; e < NEXP; e++) {
            float fi = (float)g_cnt[e] / (float)(TOKENS * TOPK);
            lb += fi * pi[e];
            tail[2 + e] = fi;
        }
        tail[1] = (float)NEXP * lb;
    }
}

// ---------------- host ----------------
extern "C" void kernel_launch(void* const* d_in, const int* in_sizes, int n_in,
                              void* d_out, int out_size) {
    const float* x  = (const float*)d_in[0];
    const float* rw = (const float*)d_in[1];
    const float* w1 = (const float*)d_in[2];
    const float* w2 = (const float*)d_in[3];
    float* out = (float*)d_out;

    void *p_cnt, *p_ptok, *p_xg, *p_h, *p_w1t, *p_w2t;
    cudaGetSymbolAddress(&p_cnt,  g_cnt);
    cudaGetSymbolAddress(&p_ptok, g_pair_tok);
    cudaGetSymbolAddress(&p_xg,   g_xg);
    cudaGetSymbolAddress(&p_h,    g_h);
    cudaGetSymbolAddress(&p_w1t,  g_w1t);
    cudaGetSymbolAddress(&p_w2t,  g_w2t);

    cudaFuncSetAttribute(gemm_tc<true>,  cudaFuncAttributeMaxDynamicSharedMemorySize, SMEM_SZ);
    cudaFuncSetAttribute(gemm_tc<false>, cudaFuncAttributeMaxDynamicSharedMemorySize, SMEM_SZ);

    cudaMemsetAsync(p_cnt, 0, NEXP * sizeof(int));
    cudaMemsetAsync(p_ptok, 0xFF, CAP * sizeof(int));

    router_kernel<<<TOKENS / 8, 256>>>(x, rw);
    offsets_kernel<<<1, 32>>>();
    scatter_kernel<<<(TOKENS + 255) / 256, 256>>>();
    gather_kernel<<<CAP, 128>>>(x);

    transpose_w1<<<dim3(16384 / 32, 1024 / 32), dim3(32, 8)>>>(w1);
    transpose_w2<<<dim3(1024 / 32, 2048 / 32, NEXP), dim3(32, 8)>>>(w2);

    gemm_tc<true><<<dim3(ROW_TILES, DFFN / BN), 128, SMEM_SZ>>>(
        (const float*)p_xg, (const float*)p_w1t);
    gemm_tc<false><<<dim3(ROW_TILES, DMODEL / BN), 128, SMEM_SZ>>>(
        (const float*)p_h, (const float*)p_w2t);

    combine_kernel<<<TOKENS, 128>>>(out);
    reduce_kernel<<<1, 256>>>(out, out_size);
}

// round 5
// speedup vs baseline: 2.3313x; 1.4883x over previous
#include <cuda_runtime.h>
#include <cuda.h>
#include <cuda_bf16.h>
#include <math.h>
#include <stdint.h>

// ---------------- problem constants ----------------
#define TOKENS   8192
#define DMODEL   1024
#define NEXP     8
#define DFFN     2048
#define TOPK     2

#define BM 128
#define BN 128
#define CAP (TOKENS*TOPK + NEXP*BM)    // 17408
#define ROW_TILES (CAP/BM)             // 136

#define BK 32                           // k elements per stage chunk
#define ROWPITCH 80                     // bytes per 32-bf16 row (conflict-free ldmatrix)
#define PLANE_BYTES (128*ROWPITCH)      // 10240
#define STAGE_BYTES (4*PLANE_BYTES)     // Ahi,Alo,Bhi,Blo = 40960
#define NSTAGE 3
#define SMEM_SZ (NSTAGE*STAGE_BYTES + 512)   // 123392

// ---------------- device scratch (bf16 hi/lo planes) ----------------
__device__ __align__(1024) __nv_bfloat16 g_xg_hi[(size_t)CAP * DMODEL];
__device__ __align__(1024) __nv_bfloat16 g_xg_lo[(size_t)CAP * DMODEL];
__device__ __align__(1024) __nv_bfloat16 g_h_hi[(size_t)CAP * DFFN];
__device__ __align__(1024) __nv_bfloat16 g_h_lo[(size_t)CAP * DFFN];
__device__ __align__(1024) __nv_bfloat16 g_w1t_hi[(size_t)NEXP * DFFN * DMODEL];
__device__ __align__(1024) __nv_bfloat16 g_w1t_lo[(size_t)NEXP * DFFN * DMODEL];
__device__ __align__(1024) __nv_bfloat16 g_w2t_hi[(size_t)NEXP * DMODEL * DFFN];
__device__ __align__(1024) __nv_bfloat16 g_w2t_lo[(size_t)NEXP * DMODEL * DFFN];
__device__ __align__(1024) float g_y[(size_t)CAP * DMODEL];
__device__ int   g_pair_tok[CAP];
__device__ float g_pair_w[CAP];
__device__ int   g_tok2row[TOKENS * TOPK];
__device__ int   g_cnt[NEXP];
__device__ int   g_cursor[NEXP];
__device__ int   g_off[NEXP + 1];
__device__ float g_probs[TOKENS * NEXP];
__device__ float g_zsq[TOKENS];
__device__ int   g_sel[TOKENS * TOPK];
__device__ float g_selw[TOKENS * TOPK];

// ---------------- helpers ----------------
__device__ __forceinline__ uint32_t smem_u32(const void* p) {
    uint32_t a;
    asm("{ .reg .u64 t; cvta.to.shared.u64 t, %1; cvt.u32.u64 %0, t; }" : "=r"(a) : "l"(p));
    return a;
}

__device__ __forceinline__ void mma_bf16(float* c, const uint32_t* a, const uint32_t* b) {
    asm volatile(
        "mma.sync.aligned.m16n8k16.row.col.f32.bf16.bf16.f32 "
        "{%0,%1,%2,%3}, {%4,%5,%6,%7}, {%8,%9}, {%0,%1,%2,%3};"
        : "+f"(c[0]), "+f"(c[1]), "+f"(c[2]), "+f"(c[3])
        : "r"(a[0]), "r"(a[1]), "r"(a[2]), "r"(a[3]), "r"(b[0]), "r"(b[1]));
}

__device__ __forceinline__ void ldsm_x4(uint32_t& r0, uint32_t& r1, uint32_t& r2, uint32_t& r3,
                                        uint32_t addr) {
    asm volatile("ldmatrix.sync.aligned.m8n8.x4.shared.b16 {%0,%1,%2,%3}, [%4];"
        : "=r"(r0), "=r"(r1), "=r"(r2), "=r"(r3) : "r"(addr));
}

#define CP_ASYNC16(saddr, gaddr) \
    asm volatile("cp.async.cg.shared.global [%0], [%1], 16;" :: "r"(saddr), "l"(gaddr) : "memory")
#define CP_COMMIT() asm volatile("cp.async.commit_group;" ::: "memory")
#define CP_WAIT1()  asm volatile("cp.async.wait_group 1;" ::: "memory")

__device__ __forceinline__ float gelu_exact(float u) {
    return 0.5f * u * (1.0f + erff(u * 0.70710678118654752440f));
}

// ---------------- router: warp per token ----------------
__global__ __launch_bounds__(256) void router_kernel(const float* __restrict__ x,
                                                     const float* __restrict__ rw) {
    __shared__ float srw[NEXP * DMODEL];
    int tid = threadIdx.x;
    for (int i = tid; i < NEXP * DMODEL; i += 256) srw[i] = rw[i];
    __syncthreads();

    int warp = tid >> 5, lane = tid & 31;
    int tok = blockIdx.x * 8 + warp;
    if (tok >= TOKENS) return;

    const float* xr = x + (size_t)tok * DMODEL;
    float acc[NEXP];
#pragma unroll
    for (int e = 0; e < NEXP; e++) acc[e] = 0.f;
    for (int i = lane; i < DMODEL; i += 32) {
        float xv = xr[i];
#pragma unroll
        for (int e = 0; e < NEXP; e++) acc[e] += xv * srw[e * DMODEL + i];
    }
#pragma unroll
    for (int off = 16; off; off >>= 1)
#pragma unroll
        for (int e = 0; e < NEXP; e++)
            acc[e] += __shfl_down_sync(0xffffffffu, acc[e], off);

    if (lane == 0) {
        float m = acc[0];
#pragma unroll
        for (int e = 1; e < NEXP; e++) m = fmaxf(m, acc[e]);
        float p[NEXP], s = 0.f;
#pragma unroll
        for (int e = 0; e < NEXP; e++) { p[e] = expf(acc[e] - m); s += p[e]; }
        float inv = 1.f / s;
#pragma unroll
        for (int e = 0; e < NEXP; e++) { p[e] *= inv; g_probs[tok * NEXP + e] = p[e]; }
        float lse = logf(s) + m;
        g_zsq[tok] = lse * lse;

        int e1 = 0;
#pragma unroll
        for (int e = 1; e < NEXP; e++) if (p[e] > p[e1]) e1 = e;
        int e2 = (e1 == 0) ? 1 : 0;
#pragma unroll
        for (int e = 0; e < NEXP; e++) if (e != e1 && p[e] > p[e2]) e2 = e;

        float wsum = p[e1] + p[e2];
        g_sel[tok * 2 + 0] = e1;  g_selw[tok * 2 + 0] = p[e1] / wsum;
        g_sel[tok * 2 + 1] = e2;  g_selw[tok * 2 + 1] = p[e2] / wsum;
        atomicAdd(&g_cnt[e1], 1);
        atomicAdd(&g_cnt[e2], 1);
    }
}

__global__ void offsets_kernel() {
    if (threadIdx.x == 0 && blockIdx.x == 0) {
        int o = 0;
#pragma unroll
        for (int e = 0; e < NEXP; e++) {
            g_off[e] = o;
            o += ((g_cnt[e] + BM - 1) / BM) * BM;
            g_cursor[e] = 0;
        }
        g_off[NEXP] = o;
    }
}

__global__ void scatter_kernel() {
    int t = blockIdx.x * blockDim.x + threadIdx.x;
    if (t >= TOKENS) return;
#pragma unroll
    for (int k = 0; k < TOPK; k++) {
        int e = g_sel[t * 2 + k];
        int pos = g_off[e] + atomicAdd(&g_cursor[e], 1);
        g_pair_tok[pos] = t;
        g_pair_w[pos]   = g_selw[t * 2 + k];
        g_tok2row[t * 2 + k] = pos;
    }
}

// gather tokens into tile-row order, splitting fp32 -> bf16 hi/lo planes
__global__ __launch_bounds__(128) void gather_split(const float* __restrict__ x) {
    int r = blockIdx.x;
    int tok = g_pair_tok[r];
    __nv_bfloat162* dh = (__nv_bfloat162*)(g_xg_hi + (size_t)r * DMODEL);
    __nv_bfloat162* dl = (__nv_bfloat162*)(g_xg_lo + (size_t)r * DMODEL);
    if (tok >= 0) {
        const float2* src = (const float2*)(x + (size_t)tok * DMODEL);
        for (int i = threadIdx.x; i < DMODEL / 2; i += 128) {
            float2 v = src[i];
            __nv_bfloat162 h = __floats2bfloat162_rn(v.x, v.y);
            float2 hf = __bfloat1622float2(h);
            dh[i] = h;
            dl[i] = __floats2bfloat162_rn(v.x - hf.x, v.y - hf.y);
        }
    } else {
        __nv_bfloat162 z = __floats2bfloat162_rn(0.f, 0.f);
        for (int i = threadIdx.x; i < DMODEL / 2; i += 128) { dh[i] = z; dl[i] = z; }
    }
}

// w1 [1024][16384] -> planes [(e,n)][k]
__global__ __launch_bounds__(256) void transpose_w1_split(const float* __restrict__ in) {
    __shared__ float t[32][33];
    int c0 = blockIdx.x * 32, r0 = blockIdx.y * 32;
    int x = threadIdx.x, y = threadIdx.y;
#pragma unroll
    for (int i = 0; i < 32; i += 8) t[y + i][x] = in[(size_t)(r0 + y + i) * 16384 + c0 + x];
    __syncthreads();
#pragma unroll
    for (int i = 0; i < 32; i += 8) {
        float v = t[x][y + i];
        size_t idx = (size_t)(c0 + y + i) * 1024 + r0 + x;
        __nv_bfloat16 h = __float2bfloat16(v);
        g_w1t_hi[idx] = h;
        g_w1t_lo[idx] = __float2bfloat16(v - __bfloat162float(h));
    }
}

// w2 [e][2048][1024] -> planes [(e,n)][k]
__global__ __launch_bounds__(256) void transpose_w2_split(const float* __restrict__ in) {
    __shared__ float t[32][33];
    int e = blockIdx.z;
    int n0 = blockIdx.x * 32, k0 = blockIdx.y * 32;
    int x = threadIdx.x, y = threadIdx.y;
#pragma unroll
    for (int i = 0; i < 32; i += 8)
        t[y + i][x] = in[((size_t)e * 2048 + k0 + y + i) * 1024 + n0 + x];
    __syncthreads();
#pragma unroll
    for (int i = 0; i < 32; i += 8) {
        float v = t[x][y + i];
        size_t idx = ((size_t)e * 1024 + n0 + y + i) * 2048 + k0 + x;
        __nv_bfloat16 h = __float2bfloat16(v);
        g_w2t_hi[idx] = h;
        g_w2t_lo[idx] = __float2bfloat16(v - __bfloat162float(h));
    }
}

// ================= GEMM: 128x128 tile, pre-split bf16x3, ldmatrix =================
template <bool FFN1>
__global__ __launch_bounds__(256, 1) void gemm_bf16(const __nv_bfloat16* __restrict__ Ah,
                                                    const __nv_bfloat16* __restrict__ Al,
                                                    const __nv_bfloat16* __restrict__ Bh,
                                                    const __nv_bfloat16* __restrict__ Bl) {
    const int KDIM = FFN1 ? DMODEL : DFFN;
    const int NCH  = KDIM / BK;

    int row0 = blockIdx.x * BM;
    if (row0 >= g_off[NEXP]) return;
    int e = 0;
#pragma unroll
    for (int i = 0; i < NEXP; i++) if (row0 >= g_off[i + 1]) e = i + 1;

    const int n0 = blockIdx.y * BN;
    const int ybase = (FFN1 ? e * DFFN : e * DMODEL) + n0;
    int tid = threadIdx.x, wid = tid >> 5, lane = tid & 31;
    int wr = wid >> 2, wc = wid & 3;            // 2x4 warp grid; warp tile 64x32
    int gid = lane >> 2, tig = lane & 3;

    extern __shared__ char smem[];
    uint32_t sbase = smem_u32(smem);
    float* swt = (float*)(smem + NSTAGE * STAGE_BYTES);
    if (!FFN1 && tid < BM) swt[tid] = g_pair_w[row0 + tid];

    // ldmatrix lane address offsets
    int sel = lane >> 3, lr = lane & 7;
    uint32_t aoff = (uint32_t)((wr * 64 + (sel & 1) * 8 + lr) * ROWPITCH + (sel >> 1) * 16);
    uint32_t boff = (uint32_t)((wc * 32 + (sel >> 1) * 8 + lr) * ROWPITCH + (sel & 1) * 16);

    float c[4][4][4];
#pragma unroll
    for (int i = 0; i < 4; i++)
#pragma unroll
        for (int j = 0; j < 4; j++)
#pragma unroll
            for (int q = 0; q < 4; q++) c[i][j][q] = 0.f;

    auto fill = [&](int st, int kc) {
        uint32_t base = sbase + st * STAGE_BYTES;
        int k0 = kc * BK;
#pragma unroll
        for (int it = 0; it < 8; it++) {
            int q = tid + 256 * it;
            int arr = q >> 9;            // 0=Ahi 1=Alo 2=Bhi 3=Blo
            int rr = (q >> 2) & 127;
            int cc = q & 3;
            uint32_t dst = base + arr * PLANE_BYTES + rr * ROWPITCH + cc * 16;
            const __nv_bfloat16* src;
            if      (arr == 0) src = Ah + (size_t)(row0 + rr) * KDIM + k0 + cc * 8;
            else if (arr == 1) src = Al + (size_t)(row0 + rr) * KDIM + k0 + cc * 8;
            else if (arr == 2) src = Bh + (size_t)(ybase + rr) * KDIM + k0 + cc * 8;
            else               src = Bl + (size_t)(ybase + rr) * KDIM + k0 + cc * 8;
            CP_ASYNC16(dst, src);
        }
    };

    fill(0, 0); CP_COMMIT();
    fill(1, 1); CP_COMMIT();

    for (int kc = 0; kc < NCH; kc++) {
        CP_WAIT1();
        __syncthreads();
        if (kc + 2 < NCH) fill((kc + 2) % NSTAGE, kc + 2);
        CP_COMMIT();

        uint32_t stg = sbase + (kc % NSTAGE) * STAGE_BYTES;
#pragma unroll
        for (int kk = 0; kk < 2; kk++) {
            uint32_t ah[4][4], al[4][4], bh[4][2], bl[4][2];
#pragma unroll
            for (int i = 0; i < 4; i++) {
                uint32_t a_addr = stg + i * (16 * ROWPITCH) + kk * 32 + aoff;
                ldsm_x4(ah[i][0], ah[i][1], ah[i][2], ah[i][3], a_addr);
                ldsm_x4(al[i][0], al[i][1], al[i][2], al[i][3], a_addr + PLANE_BYTES);
            }
#pragma unroll
            for (int jp = 0; jp < 2; jp++) {
                uint32_t b_addr = stg + 2 * PLANE_BYTES + jp * (16 * ROWPITCH) + kk * 32 + boff;
                ldsm_x4(bh[jp * 2][0], bh[jp * 2][1], bh[jp * 2 + 1][0], bh[jp * 2 + 1][1], b_addr);
                ldsm_x4(bl[jp * 2][0], bl[jp * 2][1], bl[jp * 2 + 1][0], bl[jp * 2 + 1][1],
                        b_addr + PLANE_BYTES);
            }
            // three independent passes: hh, hl, lh (accumulator reuse distance = 16)
#pragma unroll
            for (int i = 0; i < 4; i++)
#pragma unroll
                for (int j = 0; j < 4; j++) mma_bf16(c[i][j], ah[i], bh[j]);
#pragma unroll
            for (int i = 0; i < 4; i++)
#pragma unroll
                for (int j = 0; j < 4; j++) mma_bf16(c[i][j], ah[i], bl[j]);
#pragma unroll
            for (int i = 0; i < 4; i++)
#pragma unroll
                for (int j = 0; j < 4; j++) mma_bf16(c[i][j], al[i], bh[j]);
        }
        __syncthreads();
    }

    // epilogue
#pragma unroll
    for (int i = 0; i < 4; i++) {
        int mr0 = wr * 64 + i * 16 + gid;
        int mr1 = mr0 + 8;
        if (FFN1) {
#pragma unroll
            for (int j = 0; j < 4; j++) {
                int col = wc * 32 + j * 8 + tig * 2;
                float u0 = gelu_exact(c[i][j][0]), u1 = gelu_exact(c[i][j][1]);
                float u2 = gelu_exact(c[i][j][2]), u3 = gelu_exact(c[i][j][3]);
                size_t i0 = (size_t)(row0 + mr0) * DFFN + n0 + col;
                size_t i1 = (size_t)(row0 + mr1) * DFFN + n0 + col;
                __nv_bfloat162 h0 = __floats2bfloat162_rn(u0, u1);
                float2 f0 = __bfloat1622float2(h0);
                *(__nv_bfloat162*)(g_h_hi + i0) = h0;
                *(__nv_bfloat162*)(g_h_lo + i0) = __floats2bfloat162_rn(u0 - f0.x, u1 - f0.y);
                __nv_bfloat162 h1 = __floats2bfloat162_rn(u2, u3);
                float2 f1 = __bfloat1622float2(h1);
                *(__nv_bfloat162*)(g_h_hi + i1) = h1;
                *(__nv_bfloat162*)(g_h_lo + i1) = __floats2bfloat162_rn(u2 - f1.x, u3 - f1.y);
            }
        } else {
            float ws0 = swt[mr0], ws1 = swt[mr1];
            float* y0 = g_y + (size_t)(row0 + mr0) * DMODEL + n0;
            float* y1 = g_y + (size_t)(row0 + mr1) * DMODEL + n0;
#pragma unroll
            for (int j = 0; j < 4; j++) {
                int col = wc * 32 + j * 8 + tig * 2;
                *(float2*)(y0 + col) = make_float2(ws0 * c[i][j][0], ws0 * c[i][j][1]);
                *(float2*)(y1 + col) = make_float2(ws1 * c[i][j][2], ws1 * c[i][j][3]);
            }
        }
    }
}

// ---------------- combine ----------------
__global__ __launch_bounds__(128) void combine_kernel(float* __restrict__ out) {
    int t = blockIdx.x;
    int ra = g_tok2row[t * 2 + 0];
    int rb = g_tok2row[t * 2 + 1];
    const float4* ya = (const float4*)(g_y + (size_t)ra * DMODEL);
    const float4* yb = (const float4*)(g_y + (size_t)rb * DMODEL);
    float4* o = (float4*)(out + (size_t)t * DMODEL);
    for (int i = threadIdx.x; i < DMODEL / 4; i += 128) {
        float4 a = ya[i], b = yb[i];
        o[i] = make_float4(a.x + b.x, a.y + b.y, a.z + b.z, a.w + b.w);
    }
}

// ---------------- aux losses ----------------
__global__ __launch_bounds__(256) void reduce_kernel(float* __restrict__ out, int out_size) {
    __shared__ float sbuf[256];
    int tid = threadIdx.x;

    float z = 0.f;
    for (int t = tid; t < TOKENS; t += 256) z += g_zsq[t];
    sbuf[tid] = z; __syncthreads();
    for (int s = 128; s; s >>= 1) { if (tid < s) sbuf[tid] += sbuf[tid + s]; __syncthreads(); }
    float zloss = sbuf[0] / (float)TOKENS;
    __syncthreads();

    float p[NEXP];
#pragma unroll
    for (int e = 0; e < NEXP; e++) p[e] = 0.f;
    for (int t = tid; t < TOKENS; t += 256) {
#pragma unroll
        for (int e = 0; e < NEXP; e++) p[e] += g_probs[t * NEXP + e];
    }
    float pi[NEXP];
#pragma unroll
    for (int e = 0; e < NEXP; e++) {
        sbuf[tid] = p[e]; __syncthreads();
        for (int s = 128; s; s >>= 1) { if (tid < s) sbuf[tid] += sbuf[tid + s]; __syncthreads(); }
        pi[e] = sbuf[0] / (float)TOKENS;
        __syncthreads();
    }

    if (tid == 0 && out_size >= TOKENS * DMODEL + 2 + NEXP) {
        float* tail = out + (size_t)TOKENS * DMODEL;
        tail[0] = zloss;
        float lb = 0.f;
#pragma unroll
        for (int e = 0; e < NEXP; e++) {
            float fi = (float)g_cnt[e] / (float)(TOKENS * TOPK);
            lb += fi * pi[e];
            tail[2 + e] = fi;
        }
        tail[1] = (float)NEXP * lb;
    }
}

// ---------------- host ----------------
extern "C" void kernel_launch(void* const* d_in, const int* in_sizes, int n_in,
                              void* d_out, int out_size) {
    const float* x  = (const float*)d_in[0];
    const float* rw = (const float*)d_in[1];
    const float* w1 = (const float*)d_in[2];
    const float* w2 = (const float*)d_in[3];
    float* out = (float*)d_out;

    void *p_cnt, *p_ptok;
    void *p_xh, *p_xl, *p_hh, *p_hl, *p_w1h, *p_w1l, *p_w2h, *p_w2l;
    cudaGetSymbolAddress(&p_cnt,  g_cnt);
    cudaGetSymbolAddress(&p_ptok, g_pair_tok);
    cudaGetSymbolAddress(&p_xh,  g_xg_hi);
    cudaGetSymbolAddress(&p_xl,  g_xg_lo);
    cudaGetSymbolAddress(&p_hh,  g_h_hi);
    cudaGetSymbolAddress(&p_hl,  g_h_lo);
    cudaGetSymbolAddress(&p_w1h, g_w1t_hi);
    cudaGetSymbolAddress(&p_w1l, g_w1t_lo);
    cudaGetSymbolAddress(&p_w2h, g_w2t_hi);
    cudaGetSymbolAddress(&p_w2l, g_w2t_lo);

    cudaFuncSetAttribute(gemm_bf16<true>,  cudaFuncAttributeMaxDynamicSharedMemorySize, SMEM_SZ);
    cudaFuncSetAttribute(gemm_bf16<false>, cudaFuncAttributeMaxDynamicSharedMemorySize, SMEM_SZ);

    cudaMemsetAsync(p_cnt, 0, NEXP * sizeof(int));
    cudaMemsetAsync(p_ptok, 0xFF, CAP * sizeof(int));

    router_kernel<<<TOKENS / 8, 256>>>(x, rw);
    offsets_kernel<<<1, 32>>>();
    scatter_kernel<<<(TOKENS + 255) / 256, 256>>>();
    gather_split<<<CAP, 128>>>(x);

    transpose_w1_split<<<dim3(16384 / 32, 1024 / 32), dim3(32, 8)>>>(w1);
    transpose_w2_split<<<dim3(1024 / 32, 2048 / 32, NEXP), dim3(32, 8)>>>(w2);

    gemm_bf16<true><<<dim3(ROW_TILES, DFFN / BN), 256, SMEM_SZ>>>(
        (const __nv_bfloat16*)p_xh, (const __nv_bfloat16*)p_xl,
        (const __nv_bfloat16*)p_w1h, (const __nv_bfloat16*)p_w1l);
    gemm_bf16<false><<<dim3(ROW_TILES, DMODEL / BN), 256, SMEM_SZ>>>(
        (const __nv_bfloat16*)p_hh, (const __nv_bfloat16*)p_hl,
        (const __nv_bfloat16*)p_w2h, (const __nv_bfloat16*)p_w2l);

    combine_kernel<<<TOKENS, 128>>>(out);
    reduce_kernel<<<1, 256>>>(out, out_size);
}

// round 6
// speedup vs baseline: 2.4438x; 1.0482x over previous
#include <cuda_runtime.h>
#include <cuda.h>
#include <cuda_bf16.h>
#include <math.h>
#include <stdint.h>

// ---------------- problem constants ----------------
#define TOKENS   8192
#define DMODEL   1024
#define NEXP     8
#define DFFN     2048
#define TOPK     2

#define BM 128
#define BN 256                          // CTA tile N
#define CAP (TOKENS*TOPK + NEXP*BM)    // 17408
#define ROW_TILES (CAP/BM)             // 136

#define BK 32                           // k elements per stage chunk
#define ROWPITCH 80                     // bytes per 32-bf16 row (conflict-free ldmatrix)
#define APLANE (128*ROWPITCH)           // 10240
#define BPLANE (256*ROWPITCH)           // 20480
#define STAGE_BYTES (2*APLANE + 2*BPLANE)   // 61440
#define NSTAGE 3
#define SMEM_SZ (NSTAGE*STAGE_BYTES + 512)  // 184832

// ---------------- device scratch (bf16 hi/lo planes) ----------------
__device__ __align__(1024) __nv_bfloat16 g_xg_hi[(size_t)CAP * DMODEL];
__device__ __align__(1024) __nv_bfloat16 g_xg_lo[(size_t)CAP * DMODEL];
__device__ __align__(1024) __nv_bfloat16 g_h_hi[(size_t)CAP * DFFN];
__device__ __align__(1024) __nv_bfloat16 g_h_lo[(size_t)CAP * DFFN];
__device__ __align__(1024) __nv_bfloat16 g_w1t_hi[(size_t)NEXP * DFFN * DMODEL];
__device__ __align__(1024) __nv_bfloat16 g_w1t_lo[(size_t)NEXP * DFFN * DMODEL];
__device__ __align__(1024) __nv_bfloat16 g_w2t_hi[(size_t)NEXP * DMODEL * DFFN];
__device__ __align__(1024) __nv_bfloat16 g_w2t_lo[(size_t)NEXP * DMODEL * DFFN];
__device__ __align__(1024) float g_y[(size_t)CAP * DMODEL];
__device__ int   g_pair_tok[CAP];
__device__ float g_pair_w[CAP];
__device__ int   g_tok2row[TOKENS * TOPK];
__device__ int   g_cnt[NEXP];
__device__ int   g_cursor[NEXP];
__device__ int   g_off[NEXP + 1];
__device__ float g_probs[TOKENS * NEXP];
__device__ float g_zsq[TOKENS];
__device__ int   g_sel[TOKENS * TOPK];
__device__ float g_selw[TOKENS * TOPK];

// ---------------- helpers ----------------
__device__ __forceinline__ uint32_t smem_u32(const void* p) {
    uint32_t a;
    asm("{ .reg .u64 t; cvta.to.shared.u64 t, %1; cvt.u32.u64 %0, t; }" : "=r"(a) : "l"(p));
    return a;
}

__device__ __forceinline__ void mma_bf16(float* c, const uint32_t* a, const uint32_t* b) {
    asm volatile(
        "mma.sync.aligned.m16n8k16.row.col.f32.bf16.bf16.f32 "
        "{%0,%1,%2,%3}, {%4,%5,%6,%7}, {%8,%9}, {%0,%1,%2,%3};"
        : "+f"(c[0]), "+f"(c[1]), "+f"(c[2]), "+f"(c[3])
        : "r"(a[0]), "r"(a[1]), "r"(a[2]), "r"(a[3]), "r"(b[0]), "r"(b[1]));
}

__device__ __forceinline__ void ldsm_x4(uint32_t& r0, uint32_t& r1, uint32_t& r2, uint32_t& r3,
                                        uint32_t addr) {
    asm volatile("ldmatrix.sync.aligned.m8n8.x4.shared.b16 {%0,%1,%2,%3}, [%4];"
        : "=r"(r0), "=r"(r1), "=r"(r2), "=r"(r3) : "r"(addr));
}

#define CP_ASYNC16(saddr, gaddr) \
    asm volatile("cp.async.cg.shared.global [%0], [%1], 16;" :: "r"(saddr), "l"(gaddr) : "memory")
#define CP_COMMIT() asm volatile("cp.async.commit_group;" ::: "memory")
#define CP_WAIT1()  asm volatile("cp.async.wait_group 1;" ::: "memory")

__device__ __forceinline__ float gelu_exact(float u) {
    return 0.5f * u * (1.0f + erff(u * 0.70710678118654752440f));
}

// ---------------- router: warp per token ----------------
__global__ __launch_bounds__(256) void router_kernel(const float* __restrict__ x,
                                                     const float* __restrict__ rw) {
    __shared__ float srw[NEXP * DMODEL];
    int tid = threadIdx.x;
    for (int i = tid; i < NEXP * DMODEL; i += 256) srw[i] = rw[i];
    __syncthreads();

    int warp = tid >> 5, lane = tid & 31;
    int tok = blockIdx.x * 8 + warp;
    if (tok >= TOKENS) return;

    const float* xr = x + (size_t)tok * DMODEL;
    float acc[NEXP];
#pragma unroll
    for (int e = 0; e < NEXP; e++) acc[e] = 0.f;
    for (int i = lane; i < DMODEL; i += 32) {
        float xv = xr[i];
#pragma unroll
        for (int e = 0; e < NEXP; e++) acc[e] += xv * srw[e * DMODEL + i];
    }
#pragma unroll
    for (int off = 16; off; off >>= 1)
#pragma unroll
        for (int e = 0; e < NEXP; e++)
            acc[e] += __shfl_down_sync(0xffffffffu, acc[e], off);

    if (lane == 0) {
        float m = acc[0];
#pragma unroll
        for (int e = 1; e < NEXP; e++) m = fmaxf(m, acc[e]);
        float p[NEXP], s = 0.f;
#pragma unroll
        for (int e = 0; e < NEXP; e++) { p[e] = expf(acc[e] - m); s += p[e]; }
        float inv = 1.f / s;
#pragma unroll
        for (int e = 0; e < NEXP; e++) { p[e] *= inv; g_probs[tok * NEXP + e] = p[e]; }
        float lse = logf(s) + m;
        g_zsq[tok] = lse * lse;

        int e1 = 0;
#pragma unroll
        for (int e = 1; e < NEXP; e++) if (p[e] > p[e1]) e1 = e;
        int e2 = (e1 == 0) ? 1 : 0;
#pragma unroll
        for (int e = 0; e < NEXP; e++) if (e != e1 && p[e] > p[e2]) e2 = e;

        float wsum = p[e1] + p[e2];
        g_sel[tok * 2 + 0] = e1;  g_selw[tok * 2 + 0] = p[e1] / wsum;
        g_sel[tok * 2 + 1] = e2;  g_selw[tok * 2 + 1] = p[e2] / wsum;
        atomicAdd(&g_cnt[e1], 1);
        atomicAdd(&g_cnt[e2], 1);
    }
}

__global__ void offsets_kernel() {
    if (threadIdx.x == 0 && blockIdx.x == 0) {
        int o = 0;
#pragma unroll
        for (int e = 0; e < NEXP; e++) {
            g_off[e] = o;
            o += ((g_cnt[e] + BM - 1) / BM) * BM;
            g_cursor[e] = 0;
        }
        g_off[NEXP] = o;
    }
}

__global__ void scatter_kernel() {
    int t = blockIdx.x * blockDim.x + threadIdx.x;
    if (t >= TOKENS) return;
#pragma unroll
    for (int k = 0; k < TOPK; k++) {
        int e = g_sel[t * 2 + k];
        int pos = g_off[e] + atomicAdd(&g_cursor[e], 1);
        g_pair_tok[pos] = t;
        g_pair_w[pos]   = g_selw[t * 2 + k];
        g_tok2row[t * 2 + k] = pos;
    }
}

// gather tokens into tile-row order, splitting fp32 -> bf16 hi/lo planes
__global__ __launch_bounds__(128) void gather_split(const float* __restrict__ x) {
    int r = blockIdx.x;
    int tok = g_pair_tok[r];
    __nv_bfloat162* dh = (__nv_bfloat162*)(g_xg_hi + (size_t)r * DMODEL);
    __nv_bfloat162* dl = (__nv_bfloat162*)(g_xg_lo + (size_t)r * DMODEL);
    if (tok >= 0) {
        const float2* src = (const float2*)(x + (size_t)tok * DMODEL);
        for (int i = threadIdx.x; i < DMODEL / 2; i += 128) {
            float2 v = src[i];
            __nv_bfloat162 h = __floats2bfloat162_rn(v.x, v.y);
            float2 hf = __bfloat1622float2(h);
            dh[i] = h;
            dl[i] = __floats2bfloat162_rn(v.x - hf.x, v.y - hf.y);
        }
    } else {
        __nv_bfloat162 z = __floats2bfloat162_rn(0.f, 0.f);
        for (int i = threadIdx.x; i < DMODEL / 2; i += 128) { dh[i] = z; dl[i] = z; }
    }
}

// w1 [1024][16384] -> planes [(e,n)][k]
__global__ __launch_bounds__(256) void transpose_w1_split(const float* __restrict__ in) {
    __shared__ float t[32][33];
    int c0 = blockIdx.x * 32, r0 = blockIdx.y * 32;
    int x = threadIdx.x, y = threadIdx.y;
#pragma unroll
    for (int i = 0; i < 32; i += 8) t[y + i][x] = in[(size_t)(r0 + y + i) * 16384 + c0 + x];
    __syncthreads();
#pragma unroll
    for (int i = 0; i < 32; i += 8) {
        float v = t[x][y + i];
        size_t idx = (size_t)(c0 + y + i) * 1024 + r0 + x;
        __nv_bfloat16 h = __float2bfloat16(v);
        g_w1t_hi[idx] = h;
        g_w1t_lo[idx] = __float2bfloat16(v - __bfloat162float(h));
    }
}

// w2 [e][2048][1024] -> planes [(e,n)][k]
__global__ __launch_bounds__(256) void transpose_w2_split(const float* __restrict__ in) {
    __shared__ float t[32][33];
    int e = blockIdx.z;
    int n0 = blockIdx.x * 32, k0 = blockIdx.y * 32;
    int x = threadIdx.x, y = threadIdx.y;
#pragma unroll
    for (int i = 0; i < 32; i += 8)
        t[y + i][x] = in[((size_t)e * 2048 + k0 + y + i) * 1024 + n0 + x];
    __syncthreads();
#pragma unroll
    for (int i = 0; i < 32; i += 8) {
        float v = t[x][y + i];
        size_t idx = ((size_t)e * 1024 + n0 + y + i) * 2048 + k0 + x;
        __nv_bfloat16 h = __float2bfloat16(v);
        g_w2t_hi[idx] = h;
        g_w2t_lo[idx] = __float2bfloat16(v - __bfloat162float(h));
    }
}

// ================= GEMM: 128x256 CTA tile, warp tile 64x64, bf16x3 =================
template <bool FFN1>
__global__ __launch_bounds__(256, 1) void gemm_bf16(const __nv_bfloat16* __restrict__ Ah,
                                                    const __nv_bfloat16* __restrict__ Al,
                                                    const __nv_bfloat16* __restrict__ Bh,
                                                    const __nv_bfloat16* __restrict__ Bl) {
    const int KDIM = FFN1 ? DMODEL : DFFN;
    const int NCH  = KDIM / BK;

    int row0 = blockIdx.x * BM;
    if (row0 >= g_off[NEXP]) return;
    int e = 0;
#pragma unroll
    for (int i = 0; i < NEXP; i++) if (row0 >= g_off[i + 1]) e = i + 1;

    const int n0 = blockIdx.y * BN;
    const int ybase = (FFN1 ? e * DFFN : e * DMODEL) + n0;
    int tid = threadIdx.x, wid = tid >> 5, lane = tid & 31;
    int wr = wid >> 2, wc = wid & 3;            // 2x4 warp grid; warp tile 64x64
    int gid = lane >> 2, tig = lane & 3;

    extern __shared__ char smem[];
    uint32_t sbase = smem_u32(smem);
    float* swt = (float*)(smem + NSTAGE * STAGE_BYTES);
    if (!FFN1 && tid < BM) swt[tid] = g_pair_w[row0 + tid];

    // ldmatrix lane address offsets
    int sel = lane >> 3, lr = lane & 7;
    uint32_t aoff = (uint32_t)((wr * 64 + (sel & 1) * 8 + lr) * ROWPITCH + (sel >> 1) * 16);
    uint32_t boff = (uint32_t)((wc * 64 + (sel >> 1) * 8 + lr) * ROWPITCH + (sel & 1) * 16);

    float c[4][8][4];
#pragma unroll
    for (int i = 0; i < 4; i++)
#pragma unroll
        for (int j = 0; j < 8; j++)
#pragma unroll
            for (int q = 0; q < 4; q++) c[i][j][q] = 0.f;

    // stage fill: 3072 x 16B per stage, 12 per thread
    auto fill = [&](int st, int kc) {
        uint32_t base = sbase + st * STAGE_BYTES;
        int k0 = kc * BK;
#pragma unroll
        for (int it = 0; it < 12; it++) {
            int q = tid + 256 * it;
            if (q < 1024) {                       // A planes: 2 x (128 rows x 4)
                int plane = q >> 9;
                int rr = (q >> 2) & 127;
                int cc = q & 3;
                uint32_t dst = base + plane * APLANE + rr * ROWPITCH + cc * 16;
                const __nv_bfloat16* src = (plane ? Al : Ah)
                    + (size_t)(row0 + rr) * KDIM + k0 + cc * 8;
                CP_ASYNC16(dst, src);
            } else {                              // B planes: 2 x (256 rows x 4)
                int qq = q - 1024;
                int plane = qq >> 10;
                int rr = (qq >> 2) & 255;
                int cc = qq & 3;
                uint32_t dst = base + 2 * APLANE + plane * BPLANE + rr * ROWPITCH + cc * 16;
                const __nv_bfloat16* src = (plane ? Bl : Bh)
                    + (size_t)(ybase + rr) * KDIM + k0 + cc * 8;
                CP_ASYNC16(dst, src);
            }
        }
    };

    fill(0, 0); CP_COMMIT();
    fill(1, 1); CP_COMMIT();

    for (int kc = 0; kc < NCH; kc++) {
        CP_WAIT1();
        __syncthreads();
        if (kc + 2 < NCH) fill((kc + 2) % NSTAGE, kc + 2);
        CP_COMMIT();

        uint32_t stg = sbase + (kc % NSTAGE) * STAGE_BYTES;
#pragma unroll
        for (int kk = 0; kk < 2; kk++) {
            uint32_t ah[4][4], al[4][4], bh[8][2], bl[8][2];
#pragma unroll
            for (int i = 0; i < 4; i++) {
                uint32_t a_addr = stg + i * (16 * ROWPITCH) + kk * 32 + aoff;
                ldsm_x4(ah[i][0], ah[i][1], ah[i][2], ah[i][3], a_addr);
                ldsm_x4(al[i][0], al[i][1], al[i][2], al[i][3], a_addr + APLANE);
            }
#pragma unroll
            for (int jp = 0; jp < 4; jp++) {
                uint32_t b_addr = stg + 2 * APLANE + jp * (16 * ROWPITCH) + kk * 32 + boff;
                ldsm_x4(bh[jp * 2][0], bh[jp * 2][1], bh[jp * 2 + 1][0], bh[jp * 2 + 1][1], b_addr);
                ldsm_x4(bl[jp * 2][0], bl[jp * 2][1], bl[jp * 2 + 1][0], bl[jp * 2 + 1][1],
                        b_addr + BPLANE);
            }
            // three independent passes: hh, hl, lh
#pragma unroll
            for (int i = 0; i < 4; i++)
#pragma unroll
                for (int j = 0; j < 8; j++) mma_bf16(c[i][j], ah[i], bh[j]);
#pragma unroll
            for (int i = 0; i < 4; i++)
#pragma unroll
                for (int j = 0; j < 8; j++) mma_bf16(c[i][j], ah[i], bl[j]);
#pragma unroll
            for (int i = 0; i < 4; i++)
#pragma unroll
                for (int j = 0; j < 8; j++) mma_bf16(c[i][j], al[i], bh[j]);
        }
        __syncthreads();
    }

    // epilogue
#pragma unroll
    for (int i = 0; i < 4; i++) {
        int mr0 = wr * 64 + i * 16 + gid;
        int mr1 = mr0 + 8;
        if (FFN1) {
#pragma unroll
            for (int j = 0; j < 8; j++) {
                int col = wc * 64 + j * 8 + tig * 2;
                float u0 = gelu_exact(c[i][j][0]), u1 = gelu_exact(c[i][j][1]);
                float u2 = gelu_exact(c[i][j][2]), u3 = gelu_exact(c[i][j][3]);
                size_t i0 = (size_t)(row0 + mr0) * DFFN + n0 + col;
                size_t i1 = (size_t)(row0 + mr1) * DFFN + n0 + col;
                __nv_bfloat162 h0 = __floats2bfloat162_rn(u0, u1);
                float2 f0 = __bfloat1622float2(h0);
                *(__nv_bfloat162*)(g_h_hi + i0) = h0;
                *(__nv_bfloat162*)(g_h_lo + i0) = __floats2bfloat162_rn(u0 - f0.x, u1 - f0.y);
                __nv_bfloat162 h1 = __floats2bfloat162_rn(u2, u3);
                float2 f1 = __bfloat1622float2(h1);
                *(__nv_bfloat162*)(g_h_hi + i1) = h1;
                *(__nv_bfloat162*)(g_h_lo + i1) = __floats2bfloat162_rn(u2 - f1.x, u3 - f1.y);
            }
        } else {
            float ws0 = swt[mr0], ws1 = swt[mr1];
            float* y0 = g_y + (size_t)(row0 + mr0) * DMODEL + n0;
            float* y1 = g_y + (size_t)(row0 + mr1) * DMODEL + n0;
#pragma unroll
            for (int j = 0; j < 8; j++) {
                int col = wc * 64 + j * 8 + tig * 2;
                *(float2*)(y0 + col) = make_float2(ws0 * c[i][j][0], ws0 * c[i][j][1]);
                *(float2*)(y1 + col) = make_float2(ws1 * c[i][j][2], ws1 * c[i][j][3]);
            }
        }
    }
}

// ---------------- combine ----------------
__global__ __launch_bounds__(128) void combine_kernel(float* __restrict__ out) {
    int t = blockIdx.x;
    int ra = g_tok2row[t * 2 + 0];
    int rb = g_tok2row[t * 2 + 1];
    const float4* ya = (const float4*)(g_y + (size_t)ra * DMODEL);
    const float4* yb = (const float4*)(g_y + (size_t)rb * DMODEL);
    float4* o = (float4*)(out + (size_t)t * DMODEL);
    for (int i = threadIdx.x; i < DMODEL / 4; i += 128) {
        float4 a = ya[i], b = yb[i];
        o[i] = make_float4(a.x + b.x, a.y + b.y, a.z + b.z, a.w + b.w);
    }
}

// ---------------- aux losses ----------------
__global__ __launch_bounds__(256) void reduce_kernel(float* __restrict__ out, int out_size) {
    __shared__ float sbuf[256];
    int tid = threadIdx.x;

    float z = 0.f;
    for (int t = tid; t < TOKENS; t += 256) z += g_zsq[t];
    sbuf[tid] = z; __syncthreads();
    for (int s = 128; s; s >>= 1) { if (tid < s) sbuf[tid] += sbuf[tid + s]; __syncthreads(); }
    float zloss = sbuf[0] / (float)TOKENS;
    __syncthreads();

    float p[NEXP];
#pragma unroll
    for (int e = 0; e < NEXP; e++) p[e] = 0.f;
    for (int t = tid; t < TOKENS; t += 256) {
#pragma unroll
        for (int e = 0; e < NEXP; e++) p[e] += g_probs[t * NEXP + e];
    }
    float pi[NEXP];
#pragma unroll
    for (int e = 0; e < NEXP; e++) {
        sbuf[tid] = p[e]; __syncthreads();
        for (int s = 128; s; s >>= 1) { if (tid < s) sbuf[tid] += sbuf[tid + s]; __syncthreads(); }
        pi[e] = sbuf[0] / (float)TOKENS;
        __syncthreads();
    }

    if (tid == 0 && out_size >= TOKENS * DMODEL + 2 + NEXP) {
        float* tail = out + (size_t)TOKENS * DMODEL;
        tail[0] = zloss;
        float lb = 0.f;
#pragma unroll
        for (int e = 0; e < NEXP; e++) {
            float fi = (float)g_cnt[e] / (float)(TOKENS * TOPK);
            lb += fi * pi[e];
            tail[2 + e] = fi;
        }
        tail[1] = (float)NEXP * lb;
    }
}

// ---------------- host ----------------
extern "C" void kernel_launch(void* const* d_in, const int* in_sizes, int n_in,
                              void* d_out, int out_size) {
    const float* x  = (const float*)d_in[0];
    const float* rw = (const float*)d_in[1];
    const float* w1 = (const float*)d_in[2];
    const float* w2 = (const float*)d_in[3];
    float* out = (float*)d_out;

    void *p_cnt, *p_ptok;
    void *p_xh, *p_xl, *p_hh, *p_hl, *p_w1h, *p_w1l, *p_w2h, *p_w2l;
    cudaGetSymbolAddress(&p_cnt,  g_cnt);
    cudaGetSymbolAddress(&p_ptok, g_pair_tok);
    cudaGetSymbolAddress(&p_xh,  g_xg_hi);
    cudaGetSymbolAddress(&p_xl,  g_xg_lo);
    cudaGetSymbolAddress(&p_hh,  g_h_hi);
    cudaGetSymbolAddress(&p_hl,  g_h_lo);
    cudaGetSymbolAddress(&p_w1h, g_w1t_hi);
    cudaGetSymbolAddress(&p_w1l, g_w1t_lo);
    cudaGetSymbolAddress(&p_w2h, g_w2t_hi);
    cudaGetSymbolAddress(&p_w2l, g_w2t_lo);

    cudaFuncSetAttribute(gemm_bf16<true>,  cudaFuncAttributeMaxDynamicSharedMemorySize, SMEM_SZ);
    cudaFuncSetAttribute(gemm_bf16<false>, cudaFuncAttributeMaxDynamicSharedMemorySize, SMEM_SZ);

    cudaMemsetAsync(p_cnt, 0, NEXP * sizeof(int));
    cudaMemsetAsync(p_ptok, 0xFF, CAP * sizeof(int));

    router_kernel<<<TOKENS / 8, 256>>>(x, rw);
    offsets_kernel<<<1, 32>>>();
    scatter_kernel<<<(TOKENS + 255) / 256, 256>>>();
    gather_split<<<CAP, 128>>>(x);

    transpose_w1_split<<<dim3(16384 / 32, 1024 / 32), dim3(32, 8)>>>(w1);
    transpose_w2_split<<<dim3(1024 / 32, 2048 / 32, NEXP), dim3(32, 8)>>>(w2);

    gemm_bf16<true><<<dim3(ROW_TILES, DFFN / BN), 256, SMEM_SZ>>>(
        (const __nv_bfloat16*)p_xh, (const __nv_bfloat16*)p_xl,
        (const __nv_bfloat16*)p_w1h, (const __nv_bfloat16*)p_w1l);
    gemm_bf16<false><<<dim3(ROW_TILES, DMODEL / BN), 256, SMEM_SZ>>>(
        (const __nv_bfloat16*)p_hh, (const __nv_bfloat16*)p_hl,
        (const __nv_bfloat16*)p_w2h, (const __nv_bfloat16*)p_w2l);

    combine_kernel<<<TOKENS, 128>>>(out);
    reduce_kernel<<<1, 256>>>(out, out_size);
}

// round 7
// speedup vs baseline: 2.4626x; 1.0077x over previous
#include <cuda_runtime.h>
#include <cuda.h>
#include <cuda_bf16.h>
#include <math.h>
#include <stdint.h>

// ---------------- problem constants ----------------
#define TOKENS   8192
#define DMODEL   1024
#define NEXP     8
#define DFFN     2048
#define TOPK     2

#define BM 128
#define BN 256                          // CTA tile N
#define CAP (TOKENS*TOPK + NEXP*BM)    // 17408
#define ROW_TILES (CAP/BM)             // 136

#define BK 32                           // k elements per stage chunk
#define ROWPITCH 80                     // bytes per 32-bf16 row (conflict-free ldmatrix)
#define APLANE (128*ROWPITCH)           // 10240
#define BPLANE (256*ROWPITCH)           // 20480
#define STAGE_BYTES (2*APLANE + 2*BPLANE)   // 61440
#define NSTAGE 3
#define SMEM_SZ (NSTAGE*STAGE_BYTES + 512)  // 184832

// ---------------- device scratch (bf16 hi/lo planes) ----------------
__device__ __align__(1024) __nv_bfloat16 g_xg_hi[(size_t)CAP * DMODEL];
__device__ __align__(1024) __nv_bfloat16 g_xg_lo[(size_t)CAP * DMODEL];
__device__ __align__(1024) __nv_bfloat16 g_h_hi[(size_t)CAP * DFFN];
__device__ __align__(1024) __nv_bfloat16 g_h_lo[(size_t)CAP * DFFN];
__device__ __align__(1024) __nv_bfloat16 g_w1t_hi[(size_t)NEXP * DFFN * DMODEL];
__device__ __align__(1024) __nv_bfloat16 g_w1t_lo[(size_t)NEXP * DFFN * DMODEL];
__device__ __align__(1024) __nv_bfloat16 g_w2t_hi[(size_t)NEXP * DMODEL * DFFN];
__device__ __align__(1024) __nv_bfloat16 g_w2t_lo[(size_t)NEXP * DMODEL * DFFN];
__device__ __align__(1024) float g_y[(size_t)CAP * DMODEL];
__device__ float g_pair_w[CAP];
__device__ int   g_tok2row[TOKENS * TOPK];
__device__ int   g_cnt[NEXP];
__device__ int   g_cursor[NEXP];
__device__ int   g_off[NEXP + 1];
__device__ float g_probs[TOKENS * NEXP];
__device__ float g_zsq[TOKENS];
__device__ int   g_sel[TOKENS * TOPK];
__device__ float g_selw[TOKENS * TOPK];

// ---------------- helpers ----------------
__device__ __forceinline__ uint32_t smem_u32(const void* p) {
    uint32_t a;
    asm("{ .reg .u64 t; cvta.to.shared.u64 t, %1; cvt.u32.u64 %0, t; }" : "=r"(a) : "l"(p));
    return a;
}

__device__ __forceinline__ void mma_bf16(float* c, const uint32_t* a, const uint32_t* b) {
    asm volatile(
        "mma.sync.aligned.m16n8k16.row.col.f32.bf16.bf16.f32 "
        "{%0,%1,%2,%3}, {%4,%5,%6,%7}, {%8,%9}, {%0,%1,%2,%3};"
        : "+f"(c[0]), "+f"(c[1]), "+f"(c[2]), "+f"(c[3])
        : "r"(a[0]), "r"(a[1]), "r"(a[2]), "r"(a[3]), "r"(b[0]), "r"(b[1]));
}

__device__ __forceinline__ void ldsm_x4(uint32_t& r0, uint32_t& r1, uint32_t& r2, uint32_t& r3,
                                        uint32_t addr) {
    asm volatile("ldmatrix.sync.aligned.m8n8.x4.shared.b16 {%0,%1,%2,%3}, [%4];"
        : "=r"(r0), "=r"(r1), "=r"(r2), "=r"(r3) : "r"(addr));
}

#define CP_ASYNC16(saddr, gaddr) \
    asm volatile("cp.async.cg.shared.global [%0], [%1], 16;" :: "r"(saddr), "l"(gaddr) : "memory")
#define CP_COMMIT() asm volatile("cp.async.commit_group;" ::: "memory")
#define CP_WAIT1()  asm volatile("cp.async.wait_group 1;" ::: "memory")

__device__ __forceinline__ float gelu_exact(float u) {
    return 0.5f * u * (1.0f + erff(u * 0.70710678118654752440f));
}

// ---------------- router: warp per token ----------------
__global__ __launch_bounds__(256) void router_kernel(const float* __restrict__ x,
                                                     const float* __restrict__ rw) {
    __shared__ float srw[NEXP * DMODEL];
    int tid = threadIdx.x;
    for (int i = tid; i < NEXP * DMODEL; i += 256) srw[i] = rw[i];
    __syncthreads();

    int warp = tid >> 5, lane = tid & 31;
    int tok = blockIdx.x * 8 + warp;
    if (tok >= TOKENS) return;

    const float* xr = x + (size_t)tok * DMODEL;
    float acc[NEXP];
#pragma unroll
    for (int e = 0; e < NEXP; e++) acc[e] = 0.f;
    for (int i = lane; i < DMODEL; i += 32) {
        float xv = xr[i];
#pragma unroll
        for (int e = 0; e < NEXP; e++) acc[e] += xv * srw[e * DMODEL + i];
    }
#pragma unroll
    for (int off = 16; off; off >>= 1)
#pragma unroll
        for (int e = 0; e < NEXP; e++)
            acc[e] += __shfl_down_sync(0xffffffffu, acc[e], off);

    if (lane == 0) {
        float m = acc[0];
#pragma unroll
        for (int e = 1; e < NEXP; e++) m = fmaxf(m, acc[e]);
        float p[NEXP], s = 0.f;
#pragma unroll
        for (int e = 0; e < NEXP; e++) { p[e] = expf(acc[e] - m); s += p[e]; }
        float inv = 1.f / s;
#pragma unroll
        for (int e = 0; e < NEXP; e++) { p[e] *= inv; g_probs[tok * NEXP + e] = p[e]; }
        float lse = logf(s) + m;
        g_zsq[tok] = lse * lse;

        int e1 = 0;
#pragma unroll
        for (int e = 1; e < NEXP; e++) if (p[e] > p[e1]) e1 = e;
        int e2 = (e1 == 0) ? 1 : 0;
#pragma unroll
        for (int e = 0; e < NEXP; e++) if (e != e1 && p[e] > p[e2]) e2 = e;

        float wsum = p[e1] + p[e2];
        g_sel[tok * 2 + 0] = e1;  g_selw[tok * 2 + 0] = p[e1] / wsum;
        g_sel[tok * 2 + 1] = e2;  g_selw[tok * 2 + 1] = p[e2] / wsum;
        atomicAdd(&g_cnt[e1], 1);
        atomicAdd(&g_cnt[e2], 1);
    }
}

__global__ void offsets_kernel() {
    if (threadIdx.x == 0 && blockIdx.x == 0) {
        int o = 0;
#pragma unroll
        for (int e = 0; e < NEXP; e++) {
            g_off[e] = o;
            o += ((g_cnt[e] + BM - 1) / BM) * BM;
            g_cursor[e] = 0;
        }
        g_off[NEXP] = o;
    }
}

// fused scatter + gather/split: block per token
__global__ __launch_bounds__(128) void scatter_gather(const float* __restrict__ x) {
    __shared__ int spos[2];
    int t = blockIdx.x;
    if (threadIdx.x == 0) {
#pragma unroll
        for (int k = 0; k < TOPK; k++) {
            int e = g_sel[t * 2 + k];
            int pos = g_off[e] + atomicAdd(&g_cursor[e], 1);
            g_pair_w[pos] = g_selw[t * 2 + k];
            g_tok2row[t * 2 + k] = pos;
            spos[k] = pos;
        }
    }
    __syncthreads();
    int p0 = spos[0], p1 = spos[1];
    const float2* src = (const float2*)(x + (size_t)t * DMODEL);
    __nv_bfloat162* dh0 = (__nv_bfloat162*)(g_xg_hi + (size_t)p0 * DMODEL);
    __nv_bfloat162* dl0 = (__nv_bfloat162*)(g_xg_lo + (size_t)p0 * DMODEL);
    __nv_bfloat162* dh1 = (__nv_bfloat162*)(g_xg_hi + (size_t)p1 * DMODEL);
    __nv_bfloat162* dl1 = (__nv_bfloat162*)(g_xg_lo + (size_t)p1 * DMODEL);
    for (int i = threadIdx.x; i < DMODEL / 2; i += 128) {
        float2 v = src[i];
        __nv_bfloat162 h = __floats2bfloat162_rn(v.x, v.y);
        float2 hf = __bfloat1622float2(h);
        __nv_bfloat162 l = __floats2bfloat162_rn(v.x - hf.x, v.y - hf.y);
        dh0[i] = h; dl0[i] = l;
        dh1[i] = h; dl1[i] = l;
    }
}

// w1 [1024][16384] -> planes [(e,n)][k]
__global__ __launch_bounds__(256) void transpose_w1_split(const float* __restrict__ in) {
    __shared__ float t[32][33];
    int c0 = blockIdx.x * 32, r0 = blockIdx.y * 32;
    int x = threadIdx.x, y = threadIdx.y;
#pragma unroll
    for (int i = 0; i < 32; i += 8) t[y + i][x] = in[(size_t)(r0 + y + i) * 16384 + c0 + x];
    __syncthreads();
#pragma unroll
    for (int i = 0; i < 32; i += 8) {
        float v = t[x][y + i];
        size_t idx = (size_t)(c0 + y + i) * 1024 + r0 + x;
        __nv_bfloat16 h = __float2bfloat16(v);
        g_w1t_hi[idx] = h;
        g_w1t_lo[idx] = __float2bfloat16(v - __bfloat162float(h));
    }
}

// w2 [e][2048][1024] -> planes [(e,n)][k]
__global__ __launch_bounds__(256) void transpose_w2_split(const float* __restrict__ in) {
    __shared__ float t[32][33];
    int e = blockIdx.z;
    int n0 = blockIdx.x * 32, k0 = blockIdx.y * 32;
    int x = threadIdx.x, y = threadIdx.y;
#pragma unroll
    for (int i = 0; i < 32; i += 8)
        t[y + i][x] = in[((size_t)e * 2048 + k0 + y + i) * 1024 + n0 + x];
    __syncthreads();
#pragma unroll
    for (int i = 0; i < 32; i += 8) {
        float v = t[x][y + i];
        size_t idx = ((size_t)e * 1024 + n0 + y + i) * 2048 + k0 + x;
        __nv_bfloat16 h = __float2bfloat16(v);
        g_w2t_hi[idx] = h;
        g_w2t_lo[idx] = __float2bfloat16(v - __bfloat162float(h));
    }
}

// ================= GEMM: 128x256 CTA tile, warp tile 64x64, bf16x3 =================
// grid: (x = N tiles, y = row tiles)  -> wave covers many row-blocks x all col tiles,
// so A streams once and the per-expert weight slice stays L2-resident.
template <bool FFN1>
__global__ __launch_bounds__(256, 1) void gemm_bf16(const __nv_bfloat16* __restrict__ Ah,
                                                    const __nv_bfloat16* __restrict__ Al,
                                                    const __nv_bfloat16* __restrict__ Bh,
                                                    const __nv_bfloat16* __restrict__ Bl) {
    const int KDIM = FFN1 ? DMODEL : DFFN;
    const int NCH  = KDIM / BK;

    int row0 = blockIdx.y * BM;
    if (row0 >= g_off[NEXP]) return;
    int e = 0;
#pragma unroll
    for (int i = 0; i < NEXP; i++) if (row0 >= g_off[i + 1]) e = i + 1;

    const int n0 = blockIdx.x * BN;
    const int ybase = (FFN1 ? e * DFFN : e * DMODEL) + n0;
    int tid = threadIdx.x, wid = tid >> 5, lane = tid & 31;
    int wr = wid >> 2, wc = wid & 3;            // 2x4 warp grid; warp tile 64x64
    int gid = lane >> 2, tig = lane & 3;

    extern __shared__ char smem[];
    uint32_t sbase = smem_u32(smem);
    float* swt = (float*)(smem + NSTAGE * STAGE_BYTES);
    if (!FFN1 && tid < BM) swt[tid] = g_pair_w[row0 + tid];

    // ldmatrix lane address offsets
    int sel = lane >> 3, lr = lane & 7;
    uint32_t aoff = (uint32_t)((wr * 64 + (sel & 1) * 8 + lr) * ROWPITCH + (sel >> 1) * 16);
    uint32_t boff = (uint32_t)((wc * 64 + (sel >> 1) * 8 + lr) * ROWPITCH + (sel & 1) * 16);

    float c[4][8][4];
#pragma unroll
    for (int i = 0; i < 4; i++)
#pragma unroll
        for (int j = 0; j < 8; j++)
#pragma unroll
            for (int q = 0; q < 4; q++) c[i][j][q] = 0.f;

    // stage fill: 3072 x 16B per stage, 12 per thread
    auto fill = [&](int st, int kc) {
        uint32_t base = sbase + st * STAGE_BYTES;
        int k0 = kc * BK;
#pragma unroll
        for (int it = 0; it < 12; it++) {
            int q = tid + 256 * it;
            if (q < 1024) {                       // A planes: 2 x (128 rows x 4)
                int plane = q >> 9;
                int rr = (q >> 2) & 127;
                int cc = q & 3;
                uint32_t dst = base + plane * APLANE + rr * ROWPITCH + cc * 16;
                const __nv_bfloat16* src = (plane ? Al : Ah)
                    + (size_t)(row0 + rr) * KDIM + k0 + cc * 8;
                CP_ASYNC16(dst, src);
            } else {                              // B planes: 2 x (256 rows x 4)
                int qq = q - 1024;
                int plane = qq >> 10;
                int rr = (qq >> 2) & 255;
                int cc = qq & 3;
                uint32_t dst = base + 2 * APLANE + plane * BPLANE + rr * ROWPITCH + cc * 16;
                const __nv_bfloat16* src = (plane ? Bl : Bh)
                    + (size_t)(ybase + rr) * KDIM + k0 + cc * 8;
                CP_ASYNC16(dst, src);
            }
        }
    };

    fill(0, 0); CP_COMMIT();
    fill(1, 1); CP_COMMIT();

    for (int kc = 0; kc < NCH; kc++) {
        CP_WAIT1();
        __syncthreads();
        if (kc + 2 < NCH) fill((kc + 2) % NSTAGE, kc + 2);
        CP_COMMIT();

        uint32_t stg = sbase + (kc % NSTAGE) * STAGE_BYTES;
#pragma unroll
        for (int kk = 0; kk < 2; kk++) {
            uint32_t ah[4][4], al[4][4], bh[8][2], bl[8][2];
#pragma unroll
            for (int i = 0; i < 4; i++) {
                uint32_t a_addr = stg + i * (16 * ROWPITCH) + kk * 32 + aoff;
                ldsm_x4(ah[i][0], ah[i][1], ah[i][2], ah[i][3], a_addr);
                ldsm_x4(al[i][0], al[i][1], al[i][2], al[i][3], a_addr + APLANE);
            }
#pragma unroll
            for (int jp = 0; jp < 4; jp++) {
                uint32_t b_addr = stg + 2 * APLANE + jp * (16 * ROWPITCH) + kk * 32 + boff;
                ldsm_x4(bh[jp * 2][0], bh[jp * 2][1], bh[jp * 2 + 1][0], bh[jp * 2 + 1][1], b_addr);
                ldsm_x4(bl[jp * 2][0], bl[jp * 2][1], bl[jp * 2 + 1][0], bl[jp * 2 + 1][1],
                        b_addr + BPLANE);
            }
            // three independent passes: hh, hl, lh
#pragma unroll
            for (int i = 0; i < 4; i++)
#pragma unroll
                for (int j = 0; j < 8; j++) mma_bf16(c[i][j], ah[i], bh[j]);
#pragma unroll
            for (int i = 0; i < 4; i++)
#pragma unroll
                for (int j = 0; j < 8; j++) mma_bf16(c[i][j], ah[i], bl[j]);
#pragma unroll
            for (int i = 0; i < 4; i++)
#pragma unroll
                for (int j = 0; j < 8; j++) mma_bf16(c[i][j], al[i], bh[j]);
        }
        __syncthreads();
    }

    // epilogue
#pragma unroll
    for (int i = 0; i < 4; i++) {
        int mr0 = wr * 64 + i * 16 + gid;
        int mr1 = mr0 + 8;
        if (FFN1) {
#pragma unroll
            for (int j = 0; j < 8; j++) {
                int col = wc * 64 + j * 8 + tig * 2;
                float u0 = gelu_exact(c[i][j][0]), u1 = gelu_exact(c[i][j][1]);
                float u2 = gelu_exact(c[i][j][2]), u3 = gelu_exact(c[i][j][3]);
                size_t i0 = (size_t)(row0 + mr0) * DFFN + n0 + col;
                size_t i1 = (size_t)(row0 + mr1) * DFFN + n0 + col;
                __nv_bfloat162 h0 = __floats2bfloat162_rn(u0, u1);
                float2 f0 = __bfloat1622float2(h0);
                *(__nv_bfloat162*)(g_h_hi + i0) = h0;
                *(__nv_bfloat162*)(g_h_lo + i0) = __floats2bfloat162_rn(u0 - f0.x, u1 - f0.y);
                __nv_bfloat162 h1 = __floats2bfloat162_rn(u2, u3);
                float2 f1 = __bfloat1622float2(h1);
                *(__nv_bfloat162*)(g_h_hi + i1) = h1;
                *(__nv_bfloat162*)(g_h_lo + i1) = __floats2bfloat162_rn(u2 - f1.x, u3 - f1.y);
            }
        } else {
            float ws0 = swt[mr0], ws1 = swt[mr1];
            float* y0 = g_y + (size_t)(row0 + mr0) * DMODEL + n0;
            float* y1 = g_y + (size_t)(row0 + mr1) * DMODEL + n0;
#pragma unroll
            for (int j = 0; j < 8; j++) {
                int col = wc * 64 + j * 8 + tig * 2;
                *(float2*)(y0 + col) = make_float2(ws0 * c[i][j][0], ws0 * c[i][j][1]);
                *(float2*)(y1 + col) = make_float2(ws1 * c[i][j][2], ws1 * c[i][j][3]);
            }
        }
    }
}

// ---------------- combine ----------------
__global__ __launch_bounds__(128) void combine_kernel(float* __restrict__ out) {
    int t = blockIdx.x;
    int ra = g_tok2row[t * 2 + 0];
    int rb = g_tok2row[t * 2 + 1];
    const float4* ya = (const float4*)(g_y + (size_t)ra * DMODEL);
    const float4* yb = (const float4*)(g_y + (size_t)rb * DMODEL);
    float4* o = (float4*)(out + (size_t)t * DMODEL);
    for (int i = threadIdx.x; i < DMODEL / 4; i += 128) {
        float4 a = ya[i], b = yb[i];
        o[i] = make_float4(a.x + b.x, a.y + b.y, a.z + b.z, a.w + b.w);
    }
}

// ---------------- aux losses ----------------
__global__ __launch_bounds__(256) void reduce_kernel(float* __restrict__ out, int out_size) {
    __shared__ float sbuf[256];
    int tid = threadIdx.x;

    float z = 0.f;
    for (int t = tid; t < TOKENS; t += 256) z += g_zsq[t];
    sbuf[tid] = z; __syncthreads();
    for (int s = 128; s; s >>= 1) { if (tid < s) sbuf[tid] += sbuf[tid + s]; __syncthreads(); }
    float zloss = sbuf[0] / (float)TOKENS;
    __syncthreads();

    float p[NEXP];
#pragma unroll
    for (int e = 0; e < NEXP; e++) p[e] = 0.f;
    for (int t = tid; t < TOKENS; t += 256) {
#pragma unroll
        for (int e = 0; e < NEXP; e++) p[e] += g_probs[t * NEXP + e];
    }
    float pi[NEXP];
#pragma unroll
    for (int e = 0; e < NEXP; e++) {
        sbuf[tid] = p[e]; __syncthreads();
        for (int s = 128; s; s >>= 1) { if (tid < s) sbuf[tid] += sbuf[tid + s]; __syncthreads(); }
        pi[e] = sbuf[0] / (float)TOKENS;
        __syncthreads();
    }

    if (tid == 0 && out_size >= TOKENS * DMODEL + 2 + NEXP) {
        float* tail = out + (size_t)TOKENS * DMODEL;
        tail[0] = zloss;
        float lb = 0.f;
#pragma unroll
        for (int e = 0; e < NEXP; e++) {
            float fi = (float)g_cnt[e] / (float)(TOKENS * TOPK);
            lb += fi * pi[e];
            tail[2 + e] = fi;
        }
        tail[1] = (float)NEXP * lb;
    }
}

// ---------------- host ----------------
extern "C" void kernel_launch(void* const* d_in, const int* in_sizes, int n_in,
                              void* d_out, int out_size) {
    const float* x  = (const float*)d_in[0];
    const float* rw = (const float*)d_in[1];
    const float* w1 = (const float*)d_in[2];
    const float* w2 = (const float*)d_in[3];
    float* out = (float*)d_out;

    void *p_cnt;
    void *p_xh, *p_xl, *p_hh, *p_hl, *p_w1h, *p_w1l, *p_w2h, *p_w2l;
    cudaGetSymbolAddress(&p_cnt, g_cnt);
    cudaGetSymbolAddress(&p_xh,  g_xg_hi);
    cudaGetSymbolAddress(&p_xl,  g_xg_lo);
    cudaGetSymbolAddress(&p_hh,  g_h_hi);
    cudaGetSymbolAddress(&p_hl,  g_h_lo);
    cudaGetSymbolAddress(&p_w1h, g_w1t_hi);
    cudaGetSymbolAddress(&p_w1l, g_w1t_lo);
    cudaGetSymbolAddress(&p_w2h, g_w2t_hi);
    cudaGetSymbolAddress(&p_w2l, g_w2t_lo);

    cudaFuncSetAttribute(gemm_bf16<true>,  cudaFuncAttributeMaxDynamicSharedMemorySize, SMEM_SZ);
    cudaFuncSetAttribute(gemm_bf16<false>, cudaFuncAttributeMaxDynamicSharedMemorySize, SMEM_SZ);

    // launch order chosen so gemm_bf16<true> is the 6th launch (ncu -s 5 -c 1)
    cudaMemsetAsync(p_cnt, 0, NEXP * sizeof(int));                        // 1
    router_kernel<<<TOKENS / 8, 256>>>(x, rw);                            // 2
    offsets_kernel<<<1, 32>>>();                                          // 3
    scatter_gather<<<TOKENS, 128>>>(x);                                   // 4
    transpose_w1_split<<<dim3(16384 / 32, 1024 / 32), dim3(32, 8)>>>(w1); // 5

    gemm_bf16<true><<<dim3(DFFN / BN, ROW_TILES), 256, SMEM_SZ>>>(        // 6 <- profiled
        (const __nv_bfloat16*)p_xh, (const __nv_bfloat16*)p_xl,
        (const __nv_bfloat16*)p_w1h, (const __nv_bfloat16*)p_w1l);

    transpose_w2_split<<<dim3(1024 / 32, 2048 / 32, NEXP), dim3(32, 8)>>>(w2); // 7

    gemm_bf16<false><<<dim3(DMODEL / BN, ROW_TILES), 256, SMEM_SZ>>>(     // 8
        (const __nv_bfloat16*)p_hh, (const __nv_bfloat16*)p_hl,
        (const __nv_bfloat16*)p_w2h, (const __nv_bfloat16*)p_w2l);

    combine_kernel<<<TOKENS, 128>>>(out);                                 // 9
    reduce_kernel<<<1, 256>>>(out, out_size);                             // 10
}